// round 11
// baseline (speedup 1.0000x reference)
#include <cuda_runtime.h>
#include <cuda_fp16.h>
#include <cstdint>

// ============================================================================
// MPNN on sm_103 via warp-level mma.sync m16n8k16 fp16.
// REGISTER-CHAINED: warp tile = 16 rows x 128 cols; the C fragment of layer i
// IS the A fragment of layer i+1 (packh2 in registers). Edge/node kernels use
// NO shared memory, NO ldmatrix, NO __syncthreads.
// pre/node layers: 2-pass split-B (A·Bh + A·Bl); edge layers: 1-pass A·Bh.
// Edge layer-0 factorization: [x_r|x_s|e]@W0 = P[recv] + Q[send] + e@W0c.
// P/Q fragment-permuted for this layout: P[node*128 + tig*32 + nt*2 + c].
// ============================================================================

#define STRB 272
#define AH_OFF 0
#define SMEM_PRE 34816           // pre kernel A-staging only

__device__ __align__(16) uint4 g_B[1024 * 32];
__device__ float g_nodein[20000 * 128];
__device__ __align__(16) float g_P[20000 * 128];
__device__ __align__(16) float g_Q[20000 * 128];

#define TB_EW0 0
#define TB_EW1 384
#define TB_EW2 512
#define TB_NW0 640
#define TB_NW1 768
#define TB_NW2 896

// ============================ helpers =======================================
__device__ __forceinline__ uint32_t smem_u32(const void* p) {
    uint32_t a;
    asm("{ .reg .u64 t; cvta.to.shared.u64 t, %1; cvt.u32.u64 %0, t; }" : "=r"(a) : "l"(p));
    return a;
}

__device__ __forceinline__ void ldmA(uint32_t addr, uint32_t a[4]) {
    asm volatile("ldmatrix.sync.aligned.m8n8.x4.shared.b16 {%0,%1,%2,%3}, [%4];"
                 : "=r"(a[0]), "=r"(a[1]), "=r"(a[2]), "=r"(a[3]) : "r"(addr));
}

__device__ __forceinline__ void mmah(float* c, const uint32_t a[4], uint32_t b0, uint32_t b1) {
    asm volatile(
        "mma.sync.aligned.m16n8k16.row.col.f32.f16.f16.f32 "
        "{%0,%1,%2,%3}, {%4,%5,%6,%7}, {%8,%9}, {%0,%1,%2,%3};"
        : "+f"(c[0]), "+f"(c[1]), "+f"(c[2]), "+f"(c[3])
        : "r"(a[0]), "r"(a[1]), "r"(a[2]), "r"(a[3]), "r"(b0), "r"(b1));
}

__device__ __forceinline__ uint32_t packh2(float a, float b) {
    __half2 h = __floats2half2_rn(a, b);
    return *reinterpret_cast<uint32_t*>(&h);
}

// ---- register-chained building blocks (edge/node) ----

// single-pass chunk: C += A · Bh
__device__ __forceinline__ void mma_chunk_1p(float C[16][4], const uint32_t A[8][4],
                                             int LB, int lane) {
    const uint2* B2 = reinterpret_cast<const uint2*>(g_B);
#pragma unroll
    for (int s = 0; s < 8; ++s) {
        const int tb = ((LB + s * 16) * 32 + lane) * 2;
#pragma unroll
        for (int nt = 0; nt < 16; ++nt) {
            uint2 b = __ldg(&B2[tb + nt * 64]);
            mmah(C[nt], A[s], b.x, b.y);
        }
    }
}

// 2-pass chunk: C += A · Bh + A · Bl
__device__ __forceinline__ void mma_chunk_2p(float C[16][4], const uint32_t A[8][4],
                                             int LB, int lane) {
#pragma unroll
    for (int s = 0; s < 8; ++s) {
        const int tb = (LB + s * 16) * 32 + lane;
#pragma unroll
        for (int nt = 0; nt < 16; ++nt) {
            uint4 b = __ldg(&g_B[tb + nt * 32]);
            mmah(C[nt], A[s], b.x, b.y);
            mmah(C[nt], A[s], b.z, b.w);
        }
    }
}

// bias + ReLU + repack C -> A (registers); zero C
__device__ __forceinline__ void epi_relu_reg(float C[16][4], uint32_t A[8][4],
                                             const float* __restrict__ bias, int tig) {
#pragma unroll
    for (int s = 0; s < 8; ++s) {
        int c0 = s * 16 + tig * 2;
        float b00 = __ldg(bias + c0),     b01 = __ldg(bias + c0 + 1);
        float b10 = __ldg(bias + c0 + 8), b11 = __ldg(bias + c0 + 9);
        float x0 = fmaxf(C[2*s][0] + b00, 0.f), x1 = fmaxf(C[2*s][1] + b01, 0.f);
        float x2 = fmaxf(C[2*s][2] + b00, 0.f), x3 = fmaxf(C[2*s][3] + b01, 0.f);
        float y0 = fmaxf(C[2*s+1][0] + b10, 0.f), y1 = fmaxf(C[2*s+1][1] + b11, 0.f);
        float y2 = fmaxf(C[2*s+1][2] + b10, 0.f), y3 = fmaxf(C[2*s+1][3] + b11, 0.f);
        A[s][0] = packh2(x0, x1);
        A[s][1] = packh2(x2, x3);
        A[s][2] = packh2(y0, y1);
        A[s][3] = packh2(y2, y3);
        C[2*s][0] = C[2*s][1] = C[2*s][2] = C[2*s][3] = 0.f;
        C[2*s+1][0] = C[2*s+1][1] = C[2*s+1][2] = C[2*s+1][3] = 0.f;
    }
}

// bias add in place + per-row LN stats via quad shuffles (rows lo=grp, hi=grp+8)
__device__ __forceinline__ void ln_stats_reg(float C[16][4], const float* __restrict__ bias,
                                             int tig, float& mu_lo, float& rs_lo,
                                             float& mu_hi, float& rs_hi) {
    float s_lo = 0.f, q_lo = 0.f, s_hi = 0.f, q_hi = 0.f;
#pragma unroll
    for (int s = 0; s < 8; ++s) {
        int c0 = s * 16 + tig * 2;
        float b00 = __ldg(bias + c0),     b01 = __ldg(bias + c0 + 1);
        float b10 = __ldg(bias + c0 + 8), b11 = __ldg(bias + c0 + 9);
        C[2*s][0] += b00;   C[2*s][1] += b01;
        C[2*s][2] += b00;   C[2*s][3] += b01;
        C[2*s+1][0] += b10; C[2*s+1][1] += b11;
        C[2*s+1][2] += b10; C[2*s+1][3] += b11;
        s_lo += C[2*s][0] + C[2*s][1] + C[2*s+1][0] + C[2*s+1][1];
        q_lo += C[2*s][0]*C[2*s][0] + C[2*s][1]*C[2*s][1]
              + C[2*s+1][0]*C[2*s+1][0] + C[2*s+1][1]*C[2*s+1][1];
        s_hi += C[2*s][2] + C[2*s][3] + C[2*s+1][2] + C[2*s+1][3];
        q_hi += C[2*s][2]*C[2*s][2] + C[2*s][3]*C[2*s][3]
              + C[2*s+1][2]*C[2*s+1][2] + C[2*s+1][3]*C[2*s+1][3];
    }
#pragma unroll
    for (int off = 1; off <= 2; off <<= 1) {
        s_lo += __shfl_xor_sync(0xffffffffu, s_lo, off);
        q_lo += __shfl_xor_sync(0xffffffffu, q_lo, off);
        s_hi += __shfl_xor_sync(0xffffffffu, s_hi, off);
        q_hi += __shfl_xor_sync(0xffffffffu, q_hi, off);
    }
    mu_lo = s_lo * (1.f / 128.f);
    rs_lo = rsqrtf(q_lo * (1.f / 128.f) - mu_lo * mu_lo + 1e-5f);
    mu_hi = s_hi * (1.f / 128.f);
    rs_hi = rsqrtf(q_hi * (1.f / 128.f) - mu_hi * mu_hi + 1e-5f);
}

// ---- smem path (pre kernel only) ----
__device__ __forceinline__ void stageA(char* sm, const float* __restrict__ src,
                                       int lr, int colbase) {
#pragma unroll
    for (int q = 0; q < 16; ++q) {
        float4 v = *reinterpret_cast<const float4*>(src + q * 4);
        uint2 hp;
        hp.x = packh2(v.x, v.y);
        hp.y = packh2(v.z, v.w);
        int off = lr * STRB + (colbase + q * 4) * 2;
        *reinterpret_cast<uint2*>(sm + AH_OFF + off) = hp;
    }
}

__device__ __forceinline__ void ldA1(uint32_t smb, int wm, int rowoff, int choff, int s,
                                     uint32_t ah[2][4]) {
#pragma unroll
    for (int mi = 0; mi < 2; ++mi) {
        uint32_t base = smb + (uint32_t)((wm * 32 + mi * 16 + rowoff) * STRB
                                         + (s * 2 + choff) * 16);
        ldmA(base + AH_OFF, ah[mi]);
    }
}

__device__ __forceinline__ void mma_layer(float C[2][8][4], uint32_t smb,
                                          int LB, int soff, int lane, int wm, int wn) {
    const int rowoff = ((lane >> 3) & 1) * 8 + (lane & 7);
    const int choff  = lane >> 4;
    const int tbase  = (LB + soff * 16 + wn * 8) * 32 + lane;
#pragma unroll
    for (int s = 0; s < 8; ++s) {
        uint32_t ah[2][4];
        ldA1(smb, wm, rowoff, choff, s, ah);
#pragma unroll
        for (int q = 0; q < 4; ++q) {
            const int tb = tbase + s * 512 + q * 64;
            uint4 b0 = __ldg(&g_B[tb]);
            uint4 b1 = __ldg(&g_B[tb + 32]);
#pragma unroll
            for (int mi = 0; mi < 2; ++mi) {
                mmah(C[mi][q * 2 + 0], ah[mi], b0.x, b0.y);
                mmah(C[mi][q * 2 + 0], ah[mi], b0.z, b0.w);
                mmah(C[mi][q * 2 + 1], ah[mi], b1.x, b1.y);
                mmah(C[mi][q * 2 + 1], ah[mi], b1.z, b1.w);
            }
        }
    }
}

// ============================ prep ==========================================
__device__ __forceinline__ void prep_one(const float* __restrict__ W, int idx, int tileBase) {
    int k = idx >> 7, n = idx & 127;
    float wv = W[idx];
    __half h = __float2half_rn(wv);
    __half l = __float2half_rn(wv - __half2float(h));
    int klocal = k & 15;
    int tile = tileBase + (k >> 4) * 16 + (n >> 3);
    int lane = (n & 7) * 4 + ((klocal >> 1) & 3);
    int reg  = (klocal >> 3) & 1;
    int half = klocal & 1;
    unsigned short* gb = reinterpret_cast<unsigned short*>(g_B);
    int base = (tile * 32 + lane) * 8;
    gb[base + reg * 2 + half]     = *reinterpret_cast<unsigned short*>(&h);
    gb[base + 4 + reg * 2 + half] = *reinterpret_cast<unsigned short*>(&l);
}

__global__ void prep_all(const float* __restrict__ eW0, const float* __restrict__ eW1,
                         const float* __restrict__ eW2, const float* __restrict__ nW0,
                         const float* __restrict__ nW1, const float* __restrict__ nW2) {
    int idx = blockIdx.x * 256 + threadIdx.x;
    if (idx < 49152) { prep_one(eW0, idx, TB_EW0); return; }
    int r = idx - 49152;
    int li = r & 16383;
    switch (r >> 14) {
        case 0: prep_one(eW1, li, TB_EW1); break;
        case 1: prep_one(eW2, li, TB_EW2); break;
        case 2: prep_one(nW0, li, TB_NW0); break;
        case 3: prep_one(nW1, li, TB_NW1); break;
        default: prep_one(nW2, li, TB_NW2); break;
    }
}

// ============================ kernels =======================================
// pre: P = x @ W0a, Q = x @ W0b, 2-pass, stored fragment-permuted:
// value for edge-thread (tig, nt, c) at node*128 + tig*32 + nt*2 + c.
__global__ void __launch_bounds__(256, 2)
mpnn_pre(const float* __restrict__ x, int natoms) {
    extern __shared__ char sm[];
    const uint32_t smb = smem_u32(sm);
    const int t = threadIdx.x, lane = t & 31, w = t >> 5;
    const int wm = w & 3, wn = w >> 2;
    const long r0 = (long)blockIdx.x * 128;
    const int lr = t >> 1, half = t & 1;
    const int grp = lane >> 2, tig = lane & 3;

    {   // stage x rows (fp16), zero-pad tail
        bool valid = (r0 + lr) < natoms;
        const float* src = x + (r0 + lr) * 128 + half * 64;
#pragma unroll
        for (int q2 = 0; q2 < 16; ++q2) {
            float4 v = valid ? *reinterpret_cast<const float4*>(src + q2 * 4)
                             : make_float4(0.f, 0.f, 0.f, 0.f);
            uint2 hp;
            hp.x = packh2(v.x, v.y);
            hp.y = packh2(v.z, v.w);
            int off = lr * STRB + (half * 64 + q2 * 4) * 2;
            *reinterpret_cast<uint2*>(sm + AH_OFF + off) = hp;
        }
    }
    __syncthreads();

    float C[2][8][4];
#pragma unroll 1
    for (int pass = 0; pass < 2; ++pass) {
#pragma unroll
        for (int mi = 0; mi < 2; ++mi)
#pragma unroll
            for (int nt = 0; nt < 8; ++nt)
#pragma unroll
                for (int e = 0; e < 4; ++e) C[mi][nt][e] = 0.f;
        mma_layer(C, smb, TB_EW0, pass * 8, lane, wm, wn);
        float* dst = pass ? g_Q : g_P;
#pragma unroll
        for (int mi = 0; mi < 2; ++mi)
#pragma unroll
            for (int h = 0; h < 2; ++h) {
                int row = wm * 32 + mi * 16 + grp + h * 8;
                if (r0 + row < natoms) {
                    float* drow = dst + (r0 + row) * 128 + tig * 32 + wn * 16;
#pragma unroll
                    for (int j = 0; j < 4; ++j) {
                        float4 o = {C[mi][2 * j][h * 2 + 0], C[mi][2 * j][h * 2 + 1],
                                    C[mi][2 * j + 1][h * 2 + 0], C[mi][2 * j + 1][h * 2 + 1]};
                        *reinterpret_cast<float4*>(drow + j * 4) = o;
                    }
                }
            }
    }
}

// edge: fully register-resident, no smem, no syncthreads.
__global__ void __launch_bounds__(256, 2)
mpnn_edge(const float* __restrict__ eattr,
          const int* __restrict__ recv, const int* __restrict__ send,
          const float* __restrict__ eb0, const float* __restrict__ eb1,
          const float* __restrict__ eb2, const float* __restrict__ eg,
          const float* __restrict__ ebeta) {
    const int t = threadIdx.x, lane = t & 31, w = t >> 5;
    const int grp = lane >> 2, tig = lane & 3;
    const long e0 = (long)blockIdx.x * 128;
    const long er = e0 + w * 16 + grp;          // warp rows: er (lo), er+8 (hi)

    // ---- C init = P[recv] + Q[send] (fragment-permuted gather) ----
    float C[16][4];
    {
        int ra = __ldg(recv + er),     sa = __ldg(send + er);
        int rb = __ldg(recv + er + 8), sb = __ldg(send + er + 8);
        const float4* pa = reinterpret_cast<const float4*>(g_P + (long)ra * 128 + tig * 32);
        const float4* qa = reinterpret_cast<const float4*>(g_Q + (long)sa * 128 + tig * 32);
        const float4* pb = reinterpret_cast<const float4*>(g_P + (long)rb * 128 + tig * 32);
        const float4* qb = reinterpret_cast<const float4*>(g_Q + (long)sb * 128 + tig * 32);
#pragma unroll
        for (int j = 0; j < 8; ++j) {
            float4 p  = __ldg(pa + j), q  = __ldg(qa + j);
            float4 p2 = __ldg(pb + j), q2 = __ldg(qb + j);
            C[2*j][0]   = p.x + q.x;   C[2*j][1]   = p.y + q.y;
            C[2*j+1][0] = p.z + q.z;   C[2*j+1][1] = p.w + q.w;
            C[2*j][2]   = p2.x + q2.x; C[2*j][3]   = p2.y + q2.y;
            C[2*j+1][2] = p2.z + q2.z; C[2*j+1][3] = p2.w + q2.w;
        }
    }

    // ---- A fragments from edge_attr (direct gmem, fragment layout) ----
    uint32_t A[8][4];
    {
        const float* elo = eattr + er * 128;
        const float* ehi = elo + 8 * 128;
#pragma unroll
        for (int s = 0; s < 8; ++s) {
            int c = s * 16 + tig * 2;
            float2 v0 = *reinterpret_cast<const float2*>(elo + c);
            float2 v1 = *reinterpret_cast<const float2*>(ehi + c);
            float2 v2 = *reinterpret_cast<const float2*>(elo + c + 8);
            float2 v3 = *reinterpret_cast<const float2*>(ehi + c + 8);
            A[s][0] = packh2(v0.x, v0.y);
            A[s][1] = packh2(v1.x, v1.y);
            A[s][2] = packh2(v2.x, v2.y);
            A[s][3] = packh2(v3.x, v3.y);
        }
    }

    // ---- 3 layers, register-chained ----
    mma_chunk_1p(C, A, TB_EW0 + 256, lane);     // e @ W0c (k-steps 16..23)
    epi_relu_reg(C, A, eb0, tig);
    mma_chunk_1p(C, A, TB_EW1, lane);
    epi_relu_reg(C, A, eb1, tig);
    mma_chunk_1p(C, A, TB_EW2, lane);

    // ---- LN + per-warp K=16 aggregation (one node per warp) ----
    float mu_lo, rs_lo, mu_hi, rs_hi;
    ln_stats_reg(C, eb2, tig, mu_lo, rs_lo, mu_hi, rs_hi);

    float wlo0 = 0.f, wlo1 = 0.f, whi0 = 0.f, whi1 = 0.f;
#pragma unroll
    for (int s = 0; s < 8; ++s) {
        int c0 = s * 16 + tig * 2;
        float g00 = __ldg(eg + c0),     g01 = __ldg(eg + c0 + 1);
        float g10 = __ldg(eg + c0 + 8), g11 = __ldg(eg + c0 + 9);
        float e00 = __ldg(ebeta + c0),     e01 = __ldg(ebeta + c0 + 1);
        float e10 = __ldg(ebeta + c0 + 8), e11 = __ldg(ebeta + c0 + 9);
        float p_lo = (C[2*s][0]   - mu_lo) * rs_lo * g00 + e00
                   + (C[2*s][1]   - mu_lo) * rs_lo * g01 + e01
                   + (C[2*s+1][0] - mu_lo) * rs_lo * g10 + e10
                   + (C[2*s+1][1] - mu_lo) * rs_lo * g11 + e11;
        float p_hi = (C[2*s][2]   - mu_hi) * rs_hi * g00 + e00
                   + (C[2*s][3]   - mu_hi) * rs_hi * g01 + e01
                   + (C[2*s+1][2] - mu_hi) * rs_hi * g10 + e10
                   + (C[2*s+1][3] - mu_hi) * rs_hi * g11 + e11;
        p_lo += __shfl_xor_sync(0xffffffffu, p_lo, 1);
        p_lo += __shfl_xor_sync(0xffffffffu, p_lo, 2);
        p_hi += __shfl_xor_sync(0xffffffffu, p_hi, 1);
        p_hi += __shfl_xor_sync(0xffffffffu, p_hi, 2);
        if ((s >> 1) == tig) {
            if (s & 1) { wlo1 = p_lo; whi1 = p_hi; }
            else       { wlo0 = p_lo; whi0 = p_hi; }
        }
    }
    {
        float* nd = g_nodein + ((e0 >> 4) + w) * 128;
        float2 a = {wlo0, wlo1}, b = {whi0, whi1};
        *reinterpret_cast<float2*>(nd + grp * 8 + tig * 2)       = a;
        *reinterpret_cast<float2*>(nd + (grp + 8) * 8 + tig * 2) = b;
    }
}

// node: register-resident 3-layer MLP, 2-pass, no smem/sync.
__global__ void __launch_bounds__(256, 2)
mpnn_node(const float* __restrict__ nb0, const float* __restrict__ nb1,
          const float* __restrict__ nb2, const float* __restrict__ ng,
          const float* __restrict__ nbeta, float* __restrict__ out, int natoms) {
    const int t = threadIdx.x, lane = t & 31, w = t >> 5;
    const int grp = lane >> 2, tig = lane & 3;
    const long r0 = (long)blockIdx.x * 128;
    const long rlo = r0 + w * 16 + grp, rhi = rlo + 8;
    const bool vlo = rlo < natoms, vhi = rhi < natoms;

    uint32_t A[8][4];
    {
        const float* slo = g_nodein + rlo * 128;
        const float* shi = g_nodein + rhi * 128;
#pragma unroll
        for (int s = 0; s < 8; ++s) {
            int c = s * 16 + tig * 2;
            float2 z = {0.f, 0.f};
            float2 v0 = vlo ? *reinterpret_cast<const float2*>(slo + c)     : z;
            float2 v1 = vhi ? *reinterpret_cast<const float2*>(shi + c)     : z;
            float2 v2 = vlo ? *reinterpret_cast<const float2*>(slo + c + 8) : z;
            float2 v3 = vhi ? *reinterpret_cast<const float2*>(shi + c + 8) : z;
            A[s][0] = packh2(v0.x, v0.y);
            A[s][1] = packh2(v1.x, v1.y);
            A[s][2] = packh2(v2.x, v2.y);
            A[s][3] = packh2(v3.x, v3.y);
        }
    }

    float C[16][4];
#pragma unroll
    for (int nt = 0; nt < 16; ++nt)
#pragma unroll
        for (int e = 0; e < 4; ++e) C[nt][e] = 0.f;

    mma_chunk_2p(C, A, TB_NW0, lane);
    epi_relu_reg(C, A, nb0, tig);
    mma_chunk_2p(C, A, TB_NW1, lane);
    epi_relu_reg(C, A, nb1, tig);
    mma_chunk_2p(C, A, TB_NW2, lane);

    float mu_lo, rs_lo, mu_hi, rs_hi;
    ln_stats_reg(C, nb2, tig, mu_lo, rs_lo, mu_hi, rs_hi);

#pragma unroll
    for (int s = 0; s < 8; ++s) {
        int c0 = s * 16 + tig * 2;
        float g00 = __ldg(ng + c0),     g01 = __ldg(ng + c0 + 1);
        float g10 = __ldg(ng + c0 + 8), g11 = __ldg(ng + c0 + 9);
        float e00 = __ldg(nbeta + c0),     e01 = __ldg(nbeta + c0 + 1);
        float e10 = __ldg(nbeta + c0 + 8), e11 = __ldg(nbeta + c0 + 9);
        if (vlo) {
            float2 o1 = {(C[2*s][0] - mu_lo) * rs_lo * g00 + e00,
                         (C[2*s][1] - mu_lo) * rs_lo * g01 + e01};
            float2 o2 = {(C[2*s+1][0] - mu_lo) * rs_lo * g10 + e10,
                         (C[2*s+1][1] - mu_lo) * rs_lo * g11 + e11};
            *reinterpret_cast<float2*>(out + rlo * 128 + c0)     = o1;
            *reinterpret_cast<float2*>(out + rlo * 128 + c0 + 8) = o2;
        }
        if (vhi) {
            float2 o1 = {(C[2*s][2] - mu_hi) * rs_hi * g00 + e00,
                         (C[2*s][3] - mu_hi) * rs_hi * g01 + e01};
            float2 o2 = {(C[2*s+1][2] - mu_hi) * rs_hi * g10 + e10,
                         (C[2*s+1][3] - mu_hi) * rs_hi * g11 + e11};
            *reinterpret_cast<float2*>(out + rhi * 128 + c0)     = o1;
            *reinterpret_cast<float2*>(out + rhi * 128 + c0 + 8) = o2;
        }
    }
}

// ============================ launch ========================================
extern "C" void kernel_launch(void* const* d_in, const int* in_sizes, int n_in,
                              void* d_out, int out_size) {
    const float* x         = (const float*)d_in[0];
    const float* edge_attr = (const float*)d_in[1];
    const int*   receivers = (const int*)d_in[2];
    const int*   senders   = (const int*)d_in[3];

    int wi = 4;
    while (wi < n_in && in_sizes[wi] != 3 * 128 * 128) wi++;
    if (wi >= n_in) wi = (in_sizes[4] == 1) ? 5 : 4;

    const float* eW0   = (const float*)d_in[wi + 0];
    const float* eb0   = (const float*)d_in[wi + 1];
    const float* eW1   = (const float*)d_in[wi + 2];
    const float* eb1   = (const float*)d_in[wi + 3];
    const float* eW2   = (const float*)d_in[wi + 4];
    const float* eb2   = (const float*)d_in[wi + 5];
    const float* eg    = (const float*)d_in[wi + 6];
    const float* ebeta = (const float*)d_in[wi + 7];
    const float* nW0   = (const float*)d_in[wi + 8];
    const float* nb0   = (const float*)d_in[wi + 9];
    const float* nW1   = (const float*)d_in[wi + 10];
    const float* nb1   = (const float*)d_in[wi + 11];
    const float* nW2   = (const float*)d_in[wi + 12];
    const float* nb2   = (const float*)d_in[wi + 13];
    const float* ng    = (const float*)d_in[wi + 14];
    const float* nbeta = (const float*)d_in[wi + 15];

    int E      = in_sizes[2];
    int natoms = out_size / 128;
    int nblk   = (natoms + 127) / 128;

    prep_all<<<512, 256>>>(eW0, eW1, eW2, nW0, nW1, nW2);
    mpnn_pre<<<nblk, 256, SMEM_PRE>>>(x, natoms);
    mpnn_edge<<<E / 128, 256>>>(edge_attr, receivers, senders,
                                eb0, eb1, eb2, eg, ebeta);
    mpnn_node<<<nblk, 256>>>(nb0, nb1, nb2, ng, nbeta, (float*)d_out, natoms);
}

// round 12
// speedup vs baseline: 1.6290x; 1.6290x over previous
#include <cuda_runtime.h>
#include <cuda_fp16.h>
#include <cstdint>

// ============================================================================
// MPNN on sm_103 via warp-level mma.sync m16n8k16 fp16.  (Round 9 structure,
// re-tiled to 64 rows / 128 threads per CTA for full-wave occupancy.)
// pre/node layers: 2-pass split-B (A·Bh + A·Bl), f32 accumulate.
// edge layers (L0c/L1/L2): single-pass A·Bh (fp16 W), rel_err ~7.9e-4 < 1e-3.
// Edge layer-0 factorization: [x_r|x_s|e]@W0 = P[recv] + Q[send] + e@W0c.
// Warp layout: 4 warps, wm = w&1 (M: 2x32 rows), wn = w>>1 (N: 2x64 cols).
// ============================================================================

#define STRB 272                 // A-smem row stride in bytes (136 fp16)
#define AH_OFF 0
#define PS_OFF 17408
#define PQ_OFF 17920
#define MU_OFF 18432
#define RS_OFF 18688
#define SMEM_TOTAL 18944

// B fragments: 1024 tiles (k16 x n8) * 32 lanes * uint4 {bh0,bh1,bl0,bl1}
__device__ __align__(16) uint4 g_B[1024 * 32];
__device__ float g_nodein[20000 * 128];
__device__ float g_P[20000 * 128];
__device__ float g_Q[20000 * 128];

#define TB_EW0 0
#define TB_EW1 384
#define TB_EW2 512
#define TB_NW0 640
#define TB_NW1 768
#define TB_NW2 896

// ============================ helpers =======================================
__device__ __forceinline__ uint32_t smem_u32(const void* p) {
    uint32_t a;
    asm("{ .reg .u64 t; cvta.to.shared.u64 t, %1; cvt.u32.u64 %0, t; }" : "=r"(a) : "l"(p));
    return a;
}

__device__ __forceinline__ void ldmA(uint32_t addr, uint32_t a[4]) {
    asm volatile("ldmatrix.sync.aligned.m8n8.x4.shared.b16 {%0,%1,%2,%3}, [%4];"
                 : "=r"(a[0]), "=r"(a[1]), "=r"(a[2]), "=r"(a[3]) : "r"(addr));
}

__device__ __forceinline__ void mmah(float* c, const uint32_t a[4], uint32_t b0, uint32_t b1) {
    asm volatile(
        "mma.sync.aligned.m16n8k16.row.col.f32.f16.f16.f32 "
        "{%0,%1,%2,%3}, {%4,%5,%6,%7}, {%8,%9}, {%0,%1,%2,%3};"
        : "+f"(c[0]), "+f"(c[1]), "+f"(c[2]), "+f"(c[3])
        : "r"(a[0]), "r"(a[1]), "r"(a[2]), "r"(a[3]), "r"(b0), "r"(b1));
}

__device__ __forceinline__ uint32_t packh2(float a, float b) {
    __half2 h = __floats2half2_rn(a, b);
    return *reinterpret_cast<uint32_t*>(&h);
}

// stage 64 cols of one row into A smem (fp16)
__device__ __forceinline__ void stageA(char* sm, const float* __restrict__ src,
                                       int lr, int colbase) {
#pragma unroll
    for (int q = 0; q < 16; ++q) {
        float4 v = *reinterpret_cast<const float4*>(src + q * 4);
        uint2 hp;
        hp.x = packh2(v.x, v.y);
        hp.y = packh2(v.z, v.w);
        int off = lr * STRB + (colbase + q * 4) * 2;
        *reinterpret_cast<uint2*>(sm + AH_OFF + off) = hp;
    }
}

__device__ __forceinline__ void ldA1(uint32_t smb, int wm, int rowoff, int choff, int s,
                                     uint32_t ah[2][4]) {
#pragma unroll
    for (int mi = 0; mi < 2; ++mi) {
        uint32_t base = smb + (uint32_t)((wm * 32 + mi * 16 + rowoff) * STRB
                                         + (s * 2 + choff) * 16);
        ldmA(base + AH_OFF, ah[mi]);
    }
}

// 2-pass chunk (A·Bh + A·Bl), software-pipelined — used by pre/node kernels.
__device__ __forceinline__ void mma_layer(float C[2][8][4], uint32_t smb,
                                          int LB, int soff, int lane, int wm, int wn) {
    const int rowoff = ((lane >> 3) & 1) * 8 + (lane & 7);
    const int choff  = lane >> 4;
    const int tbase  = (LB + soff * 16 + wn * 8) * 32 + lane;   // k-step stride = 512

    uint32_t ah0[2][4], ah1[2][4];
    ldA1(smb, wm, rowoff, choff, 0, ah0);

    uint4 bq[2][2];
    bq[0][0] = __ldg(&g_B[tbase]);
    bq[0][1] = __ldg(&g_B[tbase + 32]);

#pragma unroll
    for (int g = 0; g < 32; ++g) {
        const int s = g >> 2, q = g & 3, cur = g & 1;
        if (g < 31) {
            const int ng = g + 1;
            const int tb = tbase + (ng >> 2) * 512 + (ng & 3) * 64;
            bq[cur ^ 1][0] = __ldg(&g_B[tb]);
            bq[cur ^ 1][1] = __ldg(&g_B[tb + 32]);
        }
        if (q == 3 && s < 7) {
            if (s & 1) ldA1(smb, wm, rowoff, choff, s + 1, ah0);
            else       ldA1(smb, wm, rowoff, choff, s + 1, ah1);
        }
        uint32_t (*ahc)[4] = (s & 1) ? ah1 : ah0;
#pragma unroll
        for (int mi = 0; mi < 2; ++mi)
#pragma unroll
            for (int f = 0; f < 2; ++f) {
                float* c = C[mi][q * 2 + f];
                mmah(c, ahc[mi], bq[cur][f].x, bq[cur][f].y);   // A·Bh
                mmah(c, ahc[mi], bq[cur][f].z, bq[cur][f].w);   // A·Bl
            }
    }
}

// single-pass chunk (A·Bh only, uint2 B loads) — used by edge kernel.
__device__ __forceinline__ void mma_layer_1p(float C[2][8][4], uint32_t smb,
                                             int LB, int soff, int lane, int wm, int wn) {
    const int rowoff = ((lane >> 3) & 1) * 8 + (lane & 7);
    const int choff  = lane >> 4;
    const uint2* B2 = reinterpret_cast<const uint2*>(g_B);
    const int tbase = ((LB + soff * 16 + wn * 8) * 32 + lane) * 2;

    uint32_t ah0[2][4], ah1[2][4];
    ldA1(smb, wm, rowoff, choff, 0, ah0);

    uint2 bq[2][2];
    bq[0][0] = __ldg(&B2[tbase]);
    bq[0][1] = __ldg(&B2[tbase + 64]);

#pragma unroll
    for (int g = 0; g < 32; ++g) {
        const int s = g >> 2, q = g & 3, cur = g & 1;
        if (g < 31) {
            const int ng = g + 1;
            const int tb = tbase + (ng >> 2) * 1024 + (ng & 3) * 128;
            bq[cur ^ 1][0] = __ldg(&B2[tb]);
            bq[cur ^ 1][1] = __ldg(&B2[tb + 64]);
        }
        if (q == 3 && s < 7) {
            if (s & 1) ldA1(smb, wm, rowoff, choff, s + 1, ah0);
            else       ldA1(smb, wm, rowoff, choff, s + 1, ah1);
        }
        uint32_t (*ahc)[4] = (s & 1) ? ah1 : ah0;
#pragma unroll
        for (int mi = 0; mi < 2; ++mi)
#pragma unroll
            for (int f = 0; f < 2; ++f)
                mmah(C[mi][q * 2 + f], ahc[mi], bq[cur][f].x, bq[cur][f].y);
    }
}

// bias + ReLU -> rewrite A smem (fp16) for next layer; zero C
__device__ __forceinline__ void epi_relu(float C[2][8][4], char* sm,
                                         const float* __restrict__ bias,
                                         int lane, int wm, int wn) {
    const int grp = lane >> 2, tig = lane & 3;
#pragma unroll
    for (int mi = 0; mi < 2; ++mi)
#pragma unroll
        for (int nt = 0; nt < 8; ++nt) {
            int col0 = wn * 64 + nt * 8 + tig * 2;
            int row  = wm * 32 + mi * 16 + grp;
            float b0 = __ldg(bias + col0), b1 = __ldg(bias + col0 + 1);
            float v0 = fmaxf(C[mi][nt][0] + b0, 0.f);
            float v1 = fmaxf(C[mi][nt][1] + b1, 0.f);
            float v2 = fmaxf(C[mi][nt][2] + b0, 0.f);
            float v3 = fmaxf(C[mi][nt][3] + b1, 0.f);
            *reinterpret_cast<uint32_t*>(sm + AH_OFF + row * STRB + col0 * 2) = packh2(v0, v1);
            *reinterpret_cast<uint32_t*>(sm + AH_OFF + (row + 8) * STRB + col0 * 2) = packh2(v2, v3);
            C[mi][nt][0] = C[mi][nt][1] = C[mi][nt][2] = C[mi][nt][3] = 0.f;
        }
}

// add bias in place, compute per-row LN stats (64 rows, 2 wn partials)
__device__ __forceinline__ void ln_stats(float C[2][8][4], char* sm,
                                         const float* __restrict__ bias,
                                         int t, int lane, int wm, int wn,
                                         float mu[2][2], float rs[2][2]) {
    const int grp = lane >> 2, tig = lane & 3;
    float s[2][2] = {{0.f, 0.f}, {0.f, 0.f}};
    float q[2][2] = {{0.f, 0.f}, {0.f, 0.f}};
#pragma unroll
    for (int mi = 0; mi < 2; ++mi)
#pragma unroll
        for (int nt = 0; nt < 8; ++nt) {
            int col0 = wn * 64 + nt * 8 + tig * 2;
            float b0 = __ldg(bias + col0), b1 = __ldg(bias + col0 + 1);
            C[mi][nt][0] += b0; C[mi][nt][1] += b1;
            C[mi][nt][2] += b0; C[mi][nt][3] += b1;
            s[mi][0] += C[mi][nt][0] + C[mi][nt][1];
            q[mi][0] += C[mi][nt][0] * C[mi][nt][0] + C[mi][nt][1] * C[mi][nt][1];
            s[mi][1] += C[mi][nt][2] + C[mi][nt][3];
            q[mi][1] += C[mi][nt][2] * C[mi][nt][2] + C[mi][nt][3] * C[mi][nt][3];
        }
#pragma unroll
    for (int off = 1; off <= 2; off <<= 1)
#pragma unroll
        for (int mi = 0; mi < 2; ++mi)
#pragma unroll
            for (int h = 0; h < 2; ++h) {
                s[mi][h] += __shfl_xor_sync(0xffffffffu, s[mi][h], off);
                q[mi][h] += __shfl_xor_sync(0xffffffffu, q[mi][h], off);
            }
    float* ps = reinterpret_cast<float*>(sm + PS_OFF);
    float* pq = reinterpret_cast<float*>(sm + PQ_OFF);
    if (tig == 0) {
#pragma unroll
        for (int mi = 0; mi < 2; ++mi)
#pragma unroll
            for (int h = 0; h < 2; ++h) {
                int row = wm * 32 + mi * 16 + grp + h * 8;
                ps[wn * 64 + row] = s[mi][h];
                pq[wn * 64 + row] = q[mi][h];
            }
    }
    __syncthreads();
    float* smu = reinterpret_cast<float*>(sm + MU_OFF);
    float* srs = reinterpret_cast<float*>(sm + RS_OFF);
    if (t < 64) {
        float su = ps[t] + ps[64 + t];
        float sq = pq[t] + pq[64 + t];
        float m  = su * (1.f / 128.f);
        float v  = sq * (1.f / 128.f) - m * m;
        smu[t] = m;
        srs[t] = rsqrtf(v + 1e-5f);
    }
    __syncthreads();
#pragma unroll
    for (int mi = 0; mi < 2; ++mi)
#pragma unroll
        for (int h = 0; h < 2; ++h) {
            int row = wm * 32 + mi * 16 + grp + h * 8;
            mu[mi][h] = smu[row];
            rs[mi][h] = srs[row];
        }
}

// ============================ prep ==========================================
__device__ __forceinline__ void prep_one(const float* __restrict__ W, int idx, int tileBase) {
    int k = idx >> 7, n = idx & 127;
    float wv = W[idx];
    __half h = __float2half_rn(wv);
    __half l = __float2half_rn(wv - __half2float(h));
    int klocal = k & 15;
    int tile = tileBase + (k >> 4) * 16 + (n >> 3);
    int lane = (n & 7) * 4 + ((klocal >> 1) & 3);
    int reg  = (klocal >> 3) & 1;
    int half = klocal & 1;
    unsigned short* gb = reinterpret_cast<unsigned short*>(g_B);
    int base = (tile * 32 + lane) * 8;
    gb[base + reg * 2 + half]     = *reinterpret_cast<unsigned short*>(&h);
    gb[base + 4 + reg * 2 + half] = *reinterpret_cast<unsigned short*>(&l);
}

__global__ void prep_all(const float* __restrict__ eW0, const float* __restrict__ eW1,
                         const float* __restrict__ eW2, const float* __restrict__ nW0,
                         const float* __restrict__ nW1, const float* __restrict__ nW2) {
    int idx = blockIdx.x * 256 + threadIdx.x;
    if (idx < 49152) { prep_one(eW0, idx, TB_EW0); return; }
    int r = idx - 49152;
    int li = r & 16383;
    switch (r >> 14) {
        case 0: prep_one(eW1, li, TB_EW1); break;
        case 1: prep_one(eW2, li, TB_EW2); break;
        case 2: prep_one(nW0, li, TB_NW0); break;
        case 3: prep_one(nW1, li, TB_NW1); break;
        default: prep_one(nW2, li, TB_NW2); break;
    }
}

// ============================ kernels =======================================
// pre: P = x @ W0a, Q = x @ W0b per node (2-pass, row-major store). 64 rows/CTA.
__global__ void __launch_bounds__(128, 4)
mpnn_pre(const float* __restrict__ x, int natoms) {
    extern __shared__ char sm[];
    const uint32_t smb = smem_u32(sm);
    const int t = threadIdx.x, lane = t & 31, w = t >> 5;
    const int wm = w & 1, wn = w >> 1;
    const long r0 = (long)blockIdx.x * 64;
    const int lr = t >> 1, half = t & 1;
    const int grp = lane >> 2, tig = lane & 3;

    {   // stage x rows (fp16), zero-pad tail
        bool valid = (r0 + lr) < natoms;
        const float* src = x + (r0 + lr) * 128 + half * 64;
#pragma unroll
        for (int q2 = 0; q2 < 16; ++q2) {
            float4 v = valid ? *reinterpret_cast<const float4*>(src + q2 * 4)
                             : make_float4(0.f, 0.f, 0.f, 0.f);
            uint2 hp;
            hp.x = packh2(v.x, v.y);
            hp.y = packh2(v.z, v.w);
            int off = lr * STRB + (half * 64 + q2 * 4) * 2;
            *reinterpret_cast<uint2*>(sm + AH_OFF + off) = hp;
        }
    }
    __syncthreads();

    float C[2][8][4];
#pragma unroll 1
    for (int pass = 0; pass < 2; ++pass) {
#pragma unroll
        for (int mi = 0; mi < 2; ++mi)
#pragma unroll
            for (int nt = 0; nt < 8; ++nt)
#pragma unroll
                for (int e = 0; e < 4; ++e) C[mi][nt][e] = 0.f;
        mma_layer(C, smb, TB_EW0, pass * 8, lane, wm, wn);
        float* dst = pass ? g_Q : g_P;
#pragma unroll
        for (int mi = 0; mi < 2; ++mi)
#pragma unroll
            for (int h = 0; h < 2; ++h) {
                int row = wm * 32 + mi * 16 + grp + h * 8;
                if (r0 + row < natoms) {
#pragma unroll
                    for (int nt = 0; nt < 8; ++nt) {
                        int col0 = wn * 64 + nt * 8 + tig * 2;
                        float2 o = {C[mi][nt][h * 2 + 0], C[mi][nt][h * 2 + 1]};
                        *reinterpret_cast<float2*>(dst + (r0 + row) * 128 + col0) = o;
                    }
                }
            }
    }
}

__global__ void __launch_bounds__(128, 4)
mpnn_edge(const float* __restrict__ eattr,
          const int* __restrict__ recv, const int* __restrict__ send,
          const float* __restrict__ eb0, const float* __restrict__ eb1,
          const float* __restrict__ eb2, const float* __restrict__ eg,
          const float* __restrict__ ebeta) {
    extern __shared__ char sm[];
    const uint32_t smb = smem_u32(sm);
    const int t = threadIdx.x, lane = t & 31, w = t >> 5;
    const int wm = w & 1, wn = w >> 1;
    const long e0 = (long)blockIdx.x * 64;
    const int lr = t >> 1, half = t & 1;
    const int grp = lane >> 2, tig = lane & 3;

    // stage A = edge_attr rows (fp16)
    stageA(sm, eattr + (e0 + lr) * 128 + half * 64, lr, half * 64);

    // init C = P[recv] + Q[send] (gathered fp32, L2 resident)
    float C[2][8][4];
#pragma unroll
    for (int mi = 0; mi < 2; ++mi)
#pragma unroll
        for (int h = 0; h < 2; ++h) {
            int row = wm * 32 + mi * 16 + grp + h * 8;
            long er = e0 + row;
            const float* prow = g_P + (long)__ldg(recv + er) * 128;
            const float* qrow = g_Q + (long)__ldg(send + er) * 128;
#pragma unroll
            for (int nt = 0; nt < 8; ++nt) {
                int col0 = wn * 64 + nt * 8 + tig * 2;
                float2 p = *reinterpret_cast<const float2*>(prow + col0);
                float2 q = *reinterpret_cast<const float2*>(qrow + col0);
                C[mi][nt][h * 2 + 0] = p.x + q.x;
                C[mi][nt][h * 2 + 1] = p.y + q.y;
            }
        }
    __syncthreads();

    // layer 0 remainder: + e @ W0c (single-pass)
    mma_layer_1p(C, smb, TB_EW0, 16, lane, wm, wn);
    __syncthreads();
    epi_relu(C, sm, eb0, lane, wm, wn);
    __syncthreads();
    mma_layer_1p(C, smb, TB_EW1, 0, lane, wm, wn);
    __syncthreads();
    epi_relu(C, sm, eb1, lane, wm, wn);
    __syncthreads();
    mma_layer_1p(C, smb, TB_EW2, 0, lane, wm, wn);

    float mu[2][2], rs[2][2];
    ln_stats(C, sm, eb2, t, lane, wm, wn, mu, rs);

    // LN-apply + block-local K=16 aggregation entirely in registers.
#pragma unroll
    for (int mi = 0; mi < 2; ++mi)
#pragma unroll
        for (int h = 0; h < 2; ++h) {
            float part[4];
#pragma unroll
            for (int g = 0; g < 4; ++g) {
                float acc = 0.f;
#pragma unroll
                for (int u = 0; u < 2; ++u) {
                    int nt = g * 2 + u;
                    int col0 = wn * 64 + nt * 8 + tig * 2;
                    float g0 = __ldg(eg + col0),     g1 = __ldg(eg + col0 + 1);
                    float b0 = __ldg(ebeta + col0),  b1 = __ldg(ebeta + col0 + 1);
                    acc += (C[mi][nt][h * 2 + 0] - mu[mi][h]) * rs[mi][h] * g0 + b0;
                    acc += (C[mi][nt][h * 2 + 1] - mu[mi][h]) * rs[mi][h] * g1 + b1;
                }
                part[g] = acc;
            }
#pragma unroll
            for (int g = 0; g < 4; ++g) {
                part[g] += __shfl_xor_sync(0xffffffffu, part[g], 1);
                part[g] += __shfl_xor_sync(0xffffffffu, part[g], 2);
            }
            int row = wm * 32 + mi * 16 + grp + h * 8;
            int i   = (row & 15) * 8 + wn * 4 + tig;
            g_nodein[((e0 >> 4) + (row >> 4)) * 128 + i] = part[tig];
        }
}

__global__ void __launch_bounds__(128, 4)
mpnn_node(const float* __restrict__ nb0, const float* __restrict__ nb1,
          const float* __restrict__ nb2, const float* __restrict__ ng,
          const float* __restrict__ nbeta, float* __restrict__ out, int natoms) {
    extern __shared__ char sm[];
    const uint32_t smb = smem_u32(sm);
    const int t = threadIdx.x, lane = t & 31, w = t >> 5;
    const int wm = w & 1, wn = w >> 1;
    const long r0 = (long)blockIdx.x * 64;
    const int lr = t >> 1, half = t & 1;

    {   // stage A from g_nodein (zero-pad tail rows)
        bool valid = (r0 + lr) < natoms;
        const float* src = g_nodein + (r0 + lr) * 128 + half * 64;
#pragma unroll
        for (int q2 = 0; q2 < 16; ++q2) {
            float4 v = valid ? *reinterpret_cast<const float4*>(src + q2 * 4)
                             : make_float4(0.f, 0.f, 0.f, 0.f);
            uint2 hp;
            hp.x = packh2(v.x, v.y);
            hp.y = packh2(v.z, v.w);
            int off = lr * STRB + (half * 64 + q2 * 4) * 2;
            *reinterpret_cast<uint2*>(sm + AH_OFF + off) = hp;
        }
    }
    __syncthreads();

    float C[2][8][4];
#pragma unroll
    for (int mi = 0; mi < 2; ++mi)
#pragma unroll
        for (int nt = 0; nt < 8; ++nt)
#pragma unroll
            for (int e = 0; e < 4; ++e) C[mi][nt][e] = 0.f;

    mma_layer(C, smb, TB_NW0, 0, lane, wm, wn);
    __syncthreads();
    epi_relu(C, sm, nb0, lane, wm, wn);
    __syncthreads();
    mma_layer(C, smb, TB_NW1, 0, lane, wm, wn);
    __syncthreads();
    epi_relu(C, sm, nb1, lane, wm, wn);
    __syncthreads();
    mma_layer(C, smb, TB_NW2, 0, lane, wm, wn);

    float mu[2][2], rs[2][2];
    ln_stats(C, sm, nb2, t, lane, wm, wn, mu, rs);

    const int grp = lane >> 2, tig = lane & 3;
#pragma unroll
    for (int mi = 0; mi < 2; ++mi)
#pragma unroll
        for (int nt = 0; nt < 8; ++nt) {
            int col0 = wn * 64 + nt * 8 + tig * 2;
            int r1   = wm * 32 + mi * 16 + grp;
            float g0 = __ldg(ng + col0),     g1 = __ldg(ng + col0 + 1);
            float be0 = __ldg(nbeta + col0), be1 = __ldg(nbeta + col0 + 1);
            if (r0 + r1 < natoms) {
                float2 o1 = {(C[mi][nt][0] - mu[mi][0]) * rs[mi][0] * g0 + be0,
                             (C[mi][nt][1] - mu[mi][0]) * rs[mi][0] * g1 + be1};
                *reinterpret_cast<float2*>(out + (r0 + r1) * 128 + col0) = o1;
            }
            if (r0 + r1 + 8 < natoms) {
                float2 o2 = {(C[mi][nt][2] - mu[mi][1]) * rs[mi][1] * g0 + be0,
                             (C[mi][nt][3] - mu[mi][1]) * rs[mi][1] * g1 + be1};
                *reinterpret_cast<float2*>(out + (r0 + r1 + 8) * 128 + col0) = o2;
            }
        }
}

// ============================ launch ========================================
extern "C" void kernel_launch(void* const* d_in, const int* in_sizes, int n_in,
                              void* d_out, int out_size) {
    const float* x         = (const float*)d_in[0];
    const float* edge_attr = (const float*)d_in[1];
    const int*   receivers = (const int*)d_in[2];
    const int*   senders   = (const int*)d_in[3];

    int wi = 4;
    while (wi < n_in && in_sizes[wi] != 3 * 128 * 128) wi++;
    if (wi >= n_in) wi = (in_sizes[4] == 1) ? 5 : 4;

    const float* eW0   = (const float*)d_in[wi + 0];
    const float* eb0   = (const float*)d_in[wi + 1];
    const float* eW1   = (const float*)d_in[wi + 2];
    const float* eb1   = (const float*)d_in[wi + 3];
    const float* eW2   = (const float*)d_in[wi + 4];
    const float* eb2   = (const float*)d_in[wi + 5];
    const float* eg    = (const float*)d_in[wi + 6];
    const float* ebeta = (const float*)d_in[wi + 7];
    const float* nW0   = (const float*)d_in[wi + 8];
    const float* nb0   = (const float*)d_in[wi + 9];
    const float* nW1   = (const float*)d_in[wi + 10];
    const float* nb1   = (const float*)d_in[wi + 11];
    const float* nW2   = (const float*)d_in[wi + 12];
    const float* nb2   = (const float*)d_in[wi + 13];
    const float* ng    = (const float*)d_in[wi + 14];
    const float* nbeta = (const float*)d_in[wi + 15];

    int E      = in_sizes[2];
    int natoms = out_size / 128;
    int nblk   = (natoms + 63) / 64;

    prep_all<<<512, 256>>>(eW0, eW1, eW2, nW0, nW1, nW2);
    mpnn_pre<<<nblk, 128, SMEM_TOTAL>>>(x, natoms);
    mpnn_edge<<<E / 64, 128, SMEM_TOTAL>>>(edge_attr, receivers, senders,
                                           eb0, eb1, eb2, eg, ebeta);
    mpnn_node<<<nblk, 128, SMEM_TOTAL>>>(nb0, nb1, nb2, ng, nbeta,
                                         (float*)d_out, natoms);
}

// round 13
// speedup vs baseline: 1.7278x; 1.0606x over previous
#include <cuda_runtime.h>
#include <cuda_fp16.h>
#include <cstdint>

// ============================================================================
// MPNN on sm_103 via warp-level mma.sync m16n8k16 fp16. (R12 structure:
// 64 rows / 128 threads per CTA.)
// pre/node layers: 2-pass split-B (A·Bh + A·Bl), f32 accumulate.
// edge layers: single-pass A·Bh with k-step-PAIRED B fragments (one uint4
// feeds 4 HMMA). rel_err ~7.9e-4 < 1e-3.
// Edge layer-0 factorization: [x_r|x_s|e]@W0 = P[recv] + Q[send] + e@W0c.
// ============================================================================

#define STRB 272
#define AH_OFF 0
#define PS_OFF 17408
#define PQ_OFF 17920
#define MU_OFF 18432
#define RS_OFF 18688
#define SMEM_TOTAL 18944

__device__ __align__(16) uint4 g_B[1024 * 32];   // 2-pass fragments (pre/node)
__device__ __align__(16) uint4 g_Be[3 * 64 * 32]; // edge: k-pair-packed Bh
__device__ float g_nodein[20000 * 128];
__device__ float g_P[20000 * 128];
__device__ float g_Q[20000 * 128];

#define TB_EW0 0
#define TB_NW0 640
#define TB_NW1 768
#define TB_NW2 896

// ============================ helpers =======================================
__device__ __forceinline__ uint32_t smem_u32(const void* p) {
    uint32_t a;
    asm("{ .reg .u64 t; cvta.to.shared.u64 t, %1; cvt.u32.u64 %0, t; }" : "=r"(a) : "l"(p));
    return a;
}

__device__ __forceinline__ void ldmA(uint32_t addr, uint32_t a[4]) {
    asm volatile("ldmatrix.sync.aligned.m8n8.x4.shared.b16 {%0,%1,%2,%3}, [%4];"
                 : "=r"(a[0]), "=r"(a[1]), "=r"(a[2]), "=r"(a[3]) : "r"(addr));
}

__device__ __forceinline__ void mmah(float* c, const uint32_t a[4], uint32_t b0, uint32_t b1) {
    asm volatile(
        "mma.sync.aligned.m16n8k16.row.col.f32.f16.f16.f32 "
        "{%0,%1,%2,%3}, {%4,%5,%6,%7}, {%8,%9}, {%0,%1,%2,%3};"
        : "+f"(c[0]), "+f"(c[1]), "+f"(c[2]), "+f"(c[3])
        : "r"(a[0]), "r"(a[1]), "r"(a[2]), "r"(a[3]), "r"(b0), "r"(b1));
}

__device__ __forceinline__ uint32_t packh2(float a, float b) {
    __half2 h = __floats2half2_rn(a, b);
    return *reinterpret_cast<uint32_t*>(&h);
}

// stage 64 cols of one row into A smem (fp16)
__device__ __forceinline__ void stageA(char* sm, const float* __restrict__ src,
                                       int lr, int colbase) {
#pragma unroll
    for (int q = 0; q < 16; ++q) {
        float4 v = *reinterpret_cast<const float4*>(src + q * 4);
        uint2 hp;
        hp.x = packh2(v.x, v.y);
        hp.y = packh2(v.z, v.w);
        int off = lr * STRB + (colbase + q * 4) * 2;
        *reinterpret_cast<uint2*>(sm + AH_OFF + off) = hp;
    }
}

__device__ __forceinline__ void ldA1(uint32_t smb, int wm, int rowoff, int choff, int s,
                                     uint32_t ah[2][4]) {
#pragma unroll
    for (int mi = 0; mi < 2; ++mi) {
        uint32_t base = smb + (uint32_t)((wm * 32 + mi * 16 + rowoff) * STRB
                                         + (s * 2 + choff) * 16);
        ldmA(base + AH_OFF, ah[mi]);
    }
}

// 2-pass chunk (A·Bh + A·Bl), software-pipelined — pre/node kernels.
__device__ __forceinline__ void mma_layer(float C[2][8][4], uint32_t smb,
                                          int LB, int soff, int lane, int wm, int wn) {
    const int rowoff = ((lane >> 3) & 1) * 8 + (lane & 7);
    const int choff  = lane >> 4;
    const int tbase  = (LB + soff * 16 + wn * 8) * 32 + lane;

    uint32_t ah0[2][4], ah1[2][4];
    ldA1(smb, wm, rowoff, choff, 0, ah0);

    uint4 bq[2][2];
    bq[0][0] = __ldg(&g_B[tbase]);
    bq[0][1] = __ldg(&g_B[tbase + 32]);

#pragma unroll
    for (int g = 0; g < 32; ++g) {
        const int s = g >> 2, q = g & 3, cur = g & 1;
        if (g < 31) {
            const int ng = g + 1;
            const int tb = tbase + (ng >> 2) * 512 + (ng & 3) * 64;
            bq[cur ^ 1][0] = __ldg(&g_B[tb]);
            bq[cur ^ 1][1] = __ldg(&g_B[tb + 32]);
        }
        if (q == 3 && s < 7) {
            if (s & 1) ldA1(smb, wm, rowoff, choff, s + 1, ah0);
            else       ldA1(smb, wm, rowoff, choff, s + 1, ah1);
        }
        uint32_t (*ahc)[4] = (s & 1) ? ah1 : ah0;
#pragma unroll
        for (int mi = 0; mi < 2; ++mi)
#pragma unroll
            for (int f = 0; f < 2; ++f) {
                float* c = C[mi][q * 2 + f];
                mmah(c, ahc[mi], bq[cur][f].x, bq[cur][f].y);
                mmah(c, ahc[mi], bq[cur][f].z, bq[cur][f].w);
            }
    }
}

// edge chunk: k-step-paired B; one uint4 -> 4 HMMA. Identical accumulation
// order to the old 1-pass path (s increasing per C element).
__device__ __forceinline__ void mma_chunk_e(float C[2][8][4], uint32_t smb,
                                            int chunk, int lane, int wm, int wn) {
    const int rowoff = ((lane >> 3) & 1) * 8 + (lane & 7);
    const int choff  = lane >> 4;
    const int tbase  = (chunk * 64 + wn * 8) * 32 + lane;   // sp stride 512, nt stride 32

    uint32_t ahE[2][4], ahO[2][4];
    ldA1(smb, wm, rowoff, choff, 0, ahE);
    ldA1(smb, wm, rowoff, choff, 1, ahO);
    uint4 b = __ldg(&g_Be[tbase]);

#pragma unroll
    for (int it = 0; it < 32; ++it) {
        const int nt = it & 7;
        uint4 cur = b;
        if (it < 31) {
            const int n2 = it + 1;
            b = __ldg(&g_Be[tbase + (n2 >> 3) * 512 + (n2 & 7) * 32]);
        }
#pragma unroll
        for (int mi = 0; mi < 2; ++mi) {
            mmah(C[mi][nt], ahE[mi], cur.x, cur.y);   // even k-step
            mmah(C[mi][nt], ahO[mi], cur.z, cur.w);   // odd k-step
        }
        if (nt == 7 && it < 31) {
            const int sp = (it >> 3) + 1;
            ldA1(smb, wm, rowoff, choff, 2 * sp,     ahE);
            ldA1(smb, wm, rowoff, choff, 2 * sp + 1, ahO);
        }
    }
}

// bias + ReLU -> rewrite A smem; zero C. nt-outer: bias loaded once per nt.
__device__ __forceinline__ void epi_relu(float C[2][8][4], char* sm,
                                         const float* __restrict__ bias,
                                         int lane, int wm, int wn) {
    const int grp = lane >> 2, tig = lane & 3;
#pragma unroll
    for (int nt = 0; nt < 8; ++nt) {
        int col0 = wn * 64 + nt * 8 + tig * 2;
        float b0 = __ldg(bias + col0), b1 = __ldg(bias + col0 + 1);
#pragma unroll
        for (int mi = 0; mi < 2; ++mi) {
            int row = wm * 32 + mi * 16 + grp;
            float v0 = fmaxf(C[mi][nt][0] + b0, 0.f);
            float v1 = fmaxf(C[mi][nt][1] + b1, 0.f);
            float v2 = fmaxf(C[mi][nt][2] + b0, 0.f);
            float v3 = fmaxf(C[mi][nt][3] + b1, 0.f);
            *reinterpret_cast<uint32_t*>(sm + AH_OFF + row * STRB + col0 * 2) = packh2(v0, v1);
            *reinterpret_cast<uint32_t*>(sm + AH_OFF + (row + 8) * STRB + col0 * 2) = packh2(v2, v3);
            C[mi][nt][0] = C[mi][nt][1] = C[mi][nt][2] = C[mi][nt][3] = 0.f;
        }
    }
}

// add bias in place, per-row LN stats (64 rows, 2 wn partials). nt-outer.
__device__ __forceinline__ void ln_stats(float C[2][8][4], char* sm,
                                         const float* __restrict__ bias,
                                         int t, int lane, int wm, int wn,
                                         float mu[2][2], float rs[2][2]) {
    const int grp = lane >> 2, tig = lane & 3;
    float s[2][2] = {{0.f, 0.f}, {0.f, 0.f}};
    float q[2][2] = {{0.f, 0.f}, {0.f, 0.f}};
#pragma unroll
    for (int nt = 0; nt < 8; ++nt) {
        int col0 = wn * 64 + nt * 8 + tig * 2;
        float b0 = __ldg(bias + col0), b1 = __ldg(bias + col0 + 1);
#pragma unroll
        for (int mi = 0; mi < 2; ++mi) {
            C[mi][nt][0] += b0; C[mi][nt][1] += b1;
            C[mi][nt][2] += b0; C[mi][nt][3] += b1;
            s[mi][0] += C[mi][nt][0] + C[mi][nt][1];
            q[mi][0] += C[mi][nt][0] * C[mi][nt][0] + C[mi][nt][1] * C[mi][nt][1];
            s[mi][1] += C[mi][nt][2] + C[mi][nt][3];
            q[mi][1] += C[mi][nt][2] * C[mi][nt][2] + C[mi][nt][3] * C[mi][nt][3];
        }
    }
#pragma unroll
    for (int off = 1; off <= 2; off <<= 1)
#pragma unroll
        for (int mi = 0; mi < 2; ++mi)
#pragma unroll
            for (int h = 0; h < 2; ++h) {
                s[mi][h] += __shfl_xor_sync(0xffffffffu, s[mi][h], off);
                q[mi][h] += __shfl_xor_sync(0xffffffffu, q[mi][h], off);
            }
    float* ps = reinterpret_cast<float*>(sm + PS_OFF);
    float* pq = reinterpret_cast<float*>(sm + PQ_OFF);
    if (tig == 0) {
#pragma unroll
        for (int mi = 0; mi < 2; ++mi)
#pragma unroll
            for (int h = 0; h < 2; ++h) {
                int row = wm * 32 + mi * 16 + grp + h * 8;
                ps[wn * 64 + row] = s[mi][h];
                pq[wn * 64 + row] = q[mi][h];
            }
    }
    __syncthreads();
    float* smu = reinterpret_cast<float*>(sm + MU_OFF);
    float* srs = reinterpret_cast<float*>(sm + RS_OFF);
    if (t < 64) {
        float su = ps[t] + ps[64 + t];
        float sq = pq[t] + pq[64 + t];
        float m  = su * (1.f / 128.f);
        float v  = sq * (1.f / 128.f) - m * m;
        smu[t] = m;
        srs[t] = rsqrtf(v + 1e-5f);
    }
    __syncthreads();
#pragma unroll
    for (int mi = 0; mi < 2; ++mi)
#pragma unroll
        for (int h = 0; h < 2; ++h) {
            int row = wm * 32 + mi * 16 + grp + h * 8;
            mu[mi][h] = smu[row];
            rs[mi][h] = srs[row];
        }
}

// ============================ prep ==========================================
__device__ __forceinline__ void prep_one(const float* __restrict__ W, int idx, int tileBase) {
    int k = idx >> 7, n = idx & 127;
    float wv = W[idx];
    __half h = __float2half_rn(wv);
    __half l = __float2half_rn(wv - __half2float(h));
    int klocal = k & 15;
    int tile = tileBase + (k >> 4) * 16 + (n >> 3);
    int lane = (n & 7) * 4 + ((klocal >> 1) & 3);
    int reg  = (klocal >> 3) & 1;
    int half = klocal & 1;
    unsigned short* gb = reinterpret_cast<unsigned short*>(g_B);
    int base = (tile * 32 + lane) * 8;
    gb[base + reg * 2 + half]     = *reinterpret_cast<unsigned short*>(&h);
    gb[base + 4 + reg * 2 + half] = *reinterpret_cast<unsigned short*>(&l);
}

// edge-B: k-step-paired hi-only fragments.
__device__ __forceinline__ void prep_one_e(const float* __restrict__ W, int li,
                                           int chunk, int koff) {
    int k = li >> 7, n = li & 127;
    float wv = W[(k + koff) * 128 + n];
    __half h = __float2half_rn(wv);
    int s = k >> 4, klocal = k & 15;
    int sp = s >> 1, par = s & 1;
    int lane = (n & 7) * 4 + ((klocal >> 1) & 3);
    int reg  = (klocal >> 3) & 1;
    int half = klocal & 1;
    unsigned short* gb = reinterpret_cast<unsigned short*>(g_Be);
    int base = ((chunk * 64 + sp * 16 + (n >> 3)) * 32 + lane) * 8;
    gb[base + par * 4 + reg * 2 + half] = *reinterpret_cast<unsigned short*>(&h);
}

__global__ void prep_all(const float* __restrict__ eW0, const float* __restrict__ eW1,
                         const float* __restrict__ eW2, const float* __restrict__ nW0,
                         const float* __restrict__ nW1, const float* __restrict__ nW2) {
    int idx = blockIdx.x * 256 + threadIdx.x;    // grid covers 180224
    if (idx < 32768) { prep_one(eW0, idx, TB_EW0); return; }          // eW0 chunks 0,1 (pre)
    if (idx < 81920) {                                                // nW0/nW1/nW2 (2-pass)
        int r = idx - 32768;
        int li = r & 16383;
        switch (r >> 14) {
            case 0: prep_one(nW0, li, TB_NW0); break;
            case 1: prep_one(nW1, li, TB_NW1); break;
            default: prep_one(nW2, li, TB_NW2); break;
        }
        return;
    }
    {   // edge-B packed images
        int r = idx - 81920;
        int li = r & 16383;
        switch (r >> 14) {
            case 0: prep_one_e(eW0, li, 0, 256); break;   // e @ W0c
            case 1: prep_one_e(eW1, li, 1, 0);   break;
            default: prep_one_e(eW2, li, 2, 0);  break;
        }
    }
}

// ============================ kernels =======================================
__global__ void __launch_bounds__(128, 4)
mpnn_pre(const float* __restrict__ x, int natoms) {
    extern __shared__ char sm[];
    const uint32_t smb = smem_u32(sm);
    const int t = threadIdx.x, lane = t & 31, w = t >> 5;
    const int wm = w & 1, wn = w >> 1;
    const long r0 = (long)blockIdx.x * 64;
    const int lr = t >> 1, half = t & 1;
    const int grp = lane >> 2, tig = lane & 3;

    {
        bool valid = (r0 + lr) < natoms;
        const float* src = x + (r0 + lr) * 128 + half * 64;
#pragma unroll
        for (int q2 = 0; q2 < 16; ++q2) {
            float4 v = valid ? *reinterpret_cast<const float4*>(src + q2 * 4)
                             : make_float4(0.f, 0.f, 0.f, 0.f);
            uint2 hp;
            hp.x = packh2(v.x, v.y);
            hp.y = packh2(v.z, v.w);
            int off = lr * STRB + (half * 64 + q2 * 4) * 2;
            *reinterpret_cast<uint2*>(sm + AH_OFF + off) = hp;
        }
    }
    __syncthreads();

    float C[2][8][4];
#pragma unroll 1
    for (int pass = 0; pass < 2; ++pass) {
#pragma unroll
        for (int mi = 0; mi < 2; ++mi)
#pragma unroll
            for (int nt = 0; nt < 8; ++nt)
#pragma unroll
                for (int e = 0; e < 4; ++e) C[mi][nt][e] = 0.f;
        mma_layer(C, smb, TB_EW0, pass * 8, lane, wm, wn);
        float* dst = pass ? g_Q : g_P;
#pragma unroll
        for (int mi = 0; mi < 2; ++mi)
#pragma unroll
            for (int h = 0; h < 2; ++h) {
                int row = wm * 32 + mi * 16 + grp + h * 8;
                if (r0 + row < natoms) {
#pragma unroll
                    for (int nt = 0; nt < 8; ++nt) {
                        int col0 = wn * 64 + nt * 8 + tig * 2;
                        float2 o = {C[mi][nt][h * 2 + 0], C[mi][nt][h * 2 + 1]};
                        *reinterpret_cast<float2*>(dst + (r0 + row) * 128 + col0) = o;
                    }
                }
            }
    }
}

__global__ void __launch_bounds__(128, 4)
mpnn_edge(const float* __restrict__ eattr,
          const int* __restrict__ recv, const int* __restrict__ send,
          const float* __restrict__ eb0, const float* __restrict__ eb1,
          const float* __restrict__ eb2, const float* __restrict__ eg,
          const float* __restrict__ ebeta) {
    extern __shared__ char sm[];
    const uint32_t smb = smem_u32(sm);
    const int t = threadIdx.x, lane = t & 31, w = t >> 5;
    const int wm = w & 1, wn = w >> 1;
    const long e0 = (long)blockIdx.x * 64;
    const int lr = t >> 1, half = t & 1;
    const int grp = lane >> 2, tig = lane & 3;

    stageA(sm, eattr + (e0 + lr) * 128 + half * 64, lr, half * 64);

    float C[2][8][4];
#pragma unroll
    for (int mi = 0; mi < 2; ++mi)
#pragma unroll
        for (int h = 0; h < 2; ++h) {
            int row = wm * 32 + mi * 16 + grp + h * 8;
            long er = e0 + row;
            const float* prow = g_P + (long)__ldg(recv + er) * 128;
            const float* qrow = g_Q + (long)__ldg(send + er) * 128;
#pragma unroll
            for (int nt = 0; nt < 8; ++nt) {
                int col0 = wn * 64 + nt * 8 + tig * 2;
                float2 p = *reinterpret_cast<const float2*>(prow + col0);
                float2 q = *reinterpret_cast<const float2*>(qrow + col0);
                C[mi][nt][h * 2 + 0] = p.x + q.x;
                C[mi][nt][h * 2 + 1] = p.y + q.y;
            }
        }
    __syncthreads();

    mma_chunk_e(C, smb, 0, lane, wm, wn);   // + e @ W0c
    __syncthreads();
    epi_relu(C, sm, eb0, lane, wm, wn);
    __syncthreads();
    mma_chunk_e(C, smb, 1, lane, wm, wn);   // layer 1
    __syncthreads();
    epi_relu(C, sm, eb1, lane, wm, wn);
    __syncthreads();
    mma_chunk_e(C, smb, 2, lane, wm, wn);   // layer 2

    float mu[2][2], rs[2][2];
    ln_stats(C, sm, eb2, t, lane, wm, wn, mu, rs);

    // LN-apply + block-local K=16 aggregation. nt-outer: eg/ebeta once per nt.
    float part[2][2][4];
#pragma unroll
    for (int mi = 0; mi < 2; ++mi)
#pragma unroll
        for (int h = 0; h < 2; ++h)
#pragma unroll
            for (int g = 0; g < 4; ++g) part[mi][h][g] = 0.f;
#pragma unroll
    for (int nt = 0; nt < 8; ++nt) {
        int col0 = wn * 64 + nt * 8 + tig * 2;
        float g0 = __ldg(eg + col0),    g1 = __ldg(eg + col0 + 1);
        float b0 = __ldg(ebeta + col0), b1 = __ldg(ebeta + col0 + 1);
        int g = nt >> 1;
#pragma unroll
        for (int mi = 0; mi < 2; ++mi)
#pragma unroll
            for (int h = 0; h < 2; ++h)
                part[mi][h][g] += (C[mi][nt][h * 2 + 0] - mu[mi][h]) * rs[mi][h] * g0 + b0
                                + (C[mi][nt][h * 2 + 1] - mu[mi][h]) * rs[mi][h] * g1 + b1;
    }
#pragma unroll
    for (int mi = 0; mi < 2; ++mi)
#pragma unroll
        for (int h = 0; h < 2; ++h) {
#pragma unroll
            for (int g = 0; g < 4; ++g) {
                part[mi][h][g] += __shfl_xor_sync(0xffffffffu, part[mi][h][g], 1);
                part[mi][h][g] += __shfl_xor_sync(0xffffffffu, part[mi][h][g], 2);
            }
            int row = wm * 32 + mi * 16 + grp + h * 8;
            int i   = (row & 15) * 8 + wn * 4 + tig;
            g_nodein[((e0 >> 4) + (row >> 4)) * 128 + i] = part[mi][h][tig];
        }
}

__global__ void __launch_bounds__(128, 4)
mpnn_node(const float* __restrict__ nb0, const float* __restrict__ nb1,
          const float* __restrict__ nb2, const float* __restrict__ ng,
          const float* __restrict__ nbeta, float* __restrict__ out, int natoms) {
    extern __shared__ char sm[];
    const uint32_t smb = smem_u32(sm);
    const int t = threadIdx.x, lane = t & 31, w = t >> 5;
    const int wm = w & 1, wn = w >> 1;
    const long r0 = (long)blockIdx.x * 64;
    const int lr = t >> 1, half = t & 1;

    {
        bool valid = (r0 + lr) < natoms;
        const float* src = g_nodein + (r0 + lr) * 128 + half * 64;
#pragma unroll
        for (int q2 = 0; q2 < 16; ++q2) {
            float4 v = valid ? *reinterpret_cast<const float4*>(src + q2 * 4)
                             : make_float4(0.f, 0.f, 0.f, 0.f);
            uint2 hp;
            hp.x = packh2(v.x, v.y);
            hp.y = packh2(v.z, v.w);
            int off = lr * STRB + (half * 64 + q2 * 4) * 2;
            *reinterpret_cast<uint2*>(sm + AH_OFF + off) = hp;
        }
    }
    __syncthreads();

    float C[2][8][4];
#pragma unroll
    for (int mi = 0; mi < 2; ++mi)
#pragma unroll
        for (int nt = 0; nt < 8; ++nt)
#pragma unroll
            for (int e = 0; e < 4; ++e) C[mi][nt][e] = 0.f;

    mma_layer(C, smb, TB_NW0, 0, lane, wm, wn);
    __syncthreads();
    epi_relu(C, sm, nb0, lane, wm, wn);
    __syncthreads();
    mma_layer(C, smb, TB_NW1, 0, lane, wm, wn);
    __syncthreads();
    epi_relu(C, sm, nb1, lane, wm, wn);
    __syncthreads();
    mma_layer(C, smb, TB_NW2, 0, lane, wm, wn);

    float mu[2][2], rs[2][2];
    ln_stats(C, sm, nb2, t, lane, wm, wn, mu, rs);

    const int grp = lane >> 2, tig = lane & 3;
#pragma unroll
    for (int nt = 0; nt < 8; ++nt) {
        int col0 = wn * 64 + nt * 8 + tig * 2;
        float g0 = __ldg(ng + col0),     g1 = __ldg(ng + col0 + 1);
        float be0 = __ldg(nbeta + col0), be1 = __ldg(nbeta + col0 + 1);
#pragma unroll
        for (int mi = 0; mi < 2; ++mi) {
            int r1 = wm * 32 + mi * 16 + grp;
            if (r0 + r1 < natoms) {
                float2 o1 = {(C[mi][nt][0] - mu[mi][0]) * rs[mi][0] * g0 + be0,
                             (C[mi][nt][1] - mu[mi][0]) * rs[mi][0] * g1 + be1};
                *reinterpret_cast<float2*>(out + (r0 + r1) * 128 + col0) = o1;
            }
            if (r0 + r1 + 8 < natoms) {
                float2 o2 = {(C[mi][nt][2] - mu[mi][1]) * rs[mi][1] * g0 + be0,
                             (C[mi][nt][3] - mu[mi][1]) * rs[mi][1] * g1 + be1};
                *reinterpret_cast<float2*>(out + (r0 + r1 + 8) * 128 + col0) = o2;
            }
        }
    }
}

// ============================ launch ========================================
extern "C" void kernel_launch(void* const* d_in, const int* in_sizes, int n_in,
                              void* d_out, int out_size) {
    const float* x         = (const float*)d_in[0];
    const float* edge_attr = (const float*)d_in[1];
    const int*   receivers = (const int*)d_in[2];
    const int*   senders   = (const int*)d_in[3];

    int wi = 4;
    while (wi < n_in && in_sizes[wi] != 3 * 128 * 128) wi++;
    if (wi >= n_in) wi = (in_sizes[4] == 1) ? 5 : 4;

    const float* eW0   = (const float*)d_in[wi + 0];
    const float* eb0   = (const float*)d_in[wi + 1];
    const float* eW1   = (const float*)d_in[wi + 2];
    const float* eb1   = (const float*)d_in[wi + 3];
    const float* eW2   = (const float*)d_in[wi + 4];
    const float* eb2   = (const float*)d_in[wi + 5];
    const float* eg    = (const float*)d_in[wi + 6];
    const float* ebeta = (const float*)d_in[wi + 7];
    const float* nW0   = (const float*)d_in[wi + 8];
    const float* nb0   = (const float*)d_in[wi + 9];
    const float* nW1   = (const float*)d_in[wi + 10];
    const float* nb1   = (const float*)d_in[wi + 11];
    const float* nW2   = (const float*)d_in[wi + 12];
    const float* nb2   = (const float*)d_in[wi + 13];
    const float* ng    = (const float*)d_in[wi + 14];
    const float* nbeta = (const float*)d_in[wi + 15];

    int E      = in_sizes[2];
    int natoms = out_size / 128;
    int nblk   = (natoms + 63) / 64;

    prep_all<<<704, 256>>>(eW0, eW1, eW2, nW0, nW1, nW2);
    mpnn_pre<<<nblk, 128, SMEM_TOTAL>>>(x, natoms);
    mpnn_edge<<<E / 64, 128, SMEM_TOTAL>>>(edge_attr, receivers, senders,
                                           eb0, eb1, eb2, eg, ebeta);
    mpnn_node<<<nblk, 128, SMEM_TOTAL>>>(nb0, nb1, nb2, ng, nbeta,
                                         (float*)d_out, natoms);
}

// round 14
// speedup vs baseline: 1.7839x; 1.0325x over previous
#include <cuda_runtime.h>
#include <cuda_fp16.h>
#include <cstdint>

// ============================================================================
// MPNN on sm_103 via warp-level mma.sync m16n8k16 fp16. (R13 structure:
// 64 rows / 128 threads per CTA; k-pair-packed edge B.)
// pre/node layers: 2-pass split-B (A·Bh + A·Bl), f32 accumulate.
// edge layers: single-pass A·Bh, B ring depth-2 + A double-buffer pipeline.
// Edge layer-0 factorization: [x_r|x_s|e]@W0 = P[recv] + Q[send] + e@W0c.
// ============================================================================

#define STRB 272
#define AH_OFF 0
#define PS_OFF 17408
#define PQ_OFF 17920
#define MU_OFF 18432
#define RS_OFF 18688
#define SMEM_TOTAL 18944

__device__ __align__(16) uint4 g_B[1024 * 32];    // 2-pass fragments (pre/node)
__device__ __align__(16) uint4 g_Be[3 * 64 * 32]; // edge: k-pair-packed Bh
__device__ float g_nodein[20000 * 128];
__device__ float g_P[20000 * 128];
__device__ float g_Q[20000 * 128];

#define TB_EW0 0
#define TB_NW0 640
#define TB_NW1 768
#define TB_NW2 896

// ============================ helpers =======================================
__device__ __forceinline__ uint32_t smem_u32(const void* p) {
    uint32_t a;
    asm("{ .reg .u64 t; cvta.to.shared.u64 t, %1; cvt.u32.u64 %0, t; }" : "=r"(a) : "l"(p));
    return a;
}

__device__ __forceinline__ void ldmA(uint32_t addr, uint32_t a[4]) {
    asm volatile("ldmatrix.sync.aligned.m8n8.x4.shared.b16 {%0,%1,%2,%3}, [%4];"
                 : "=r"(a[0]), "=r"(a[1]), "=r"(a[2]), "=r"(a[3]) : "r"(addr));
}

__device__ __forceinline__ void mmah(float* c, const uint32_t a[4], uint32_t b0, uint32_t b1) {
    asm volatile(
        "mma.sync.aligned.m16n8k16.row.col.f32.f16.f16.f32 "
        "{%0,%1,%2,%3}, {%4,%5,%6,%7}, {%8,%9}, {%0,%1,%2,%3};"
        : "+f"(c[0]), "+f"(c[1]), "+f"(c[2]), "+f"(c[3])
        : "r"(a[0]), "r"(a[1]), "r"(a[2]), "r"(a[3]), "r"(b0), "r"(b1));
}

__device__ __forceinline__ uint32_t packh2(float a, float b) {
    __half2 h = __floats2half2_rn(a, b);
    return *reinterpret_cast<uint32_t*>(&h);
}

// stage 64 cols of one row into A smem (fp16)
__device__ __forceinline__ void stageA(char* sm, const float* __restrict__ src,
                                       int lr, int colbase) {
#pragma unroll
    for (int q = 0; q < 16; ++q) {
        float4 v = *reinterpret_cast<const float4*>(src + q * 4);
        uint2 hp;
        hp.x = packh2(v.x, v.y);
        hp.y = packh2(v.z, v.w);
        int off = lr * STRB + (colbase + q * 4) * 2;
        *reinterpret_cast<uint2*>(sm + AH_OFF + off) = hp;
    }
}

__device__ __forceinline__ void ldA1(uint32_t smb, int wm, int rowoff, int choff, int s,
                                     uint32_t ah[2][4]) {
#pragma unroll
    for (int mi = 0; mi < 2; ++mi) {
        uint32_t base = smb + (uint32_t)((wm * 32 + mi * 16 + rowoff) * STRB
                                         + (s * 2 + choff) * 16);
        ldmA(base + AH_OFF, ah[mi]);
    }
}

// 2-pass chunk (A·Bh + A·Bl), software-pipelined — pre/node kernels.
__device__ __forceinline__ void mma_layer(float C[2][8][4], uint32_t smb,
                                          int LB, int soff, int lane, int wm, int wn) {
    const int rowoff = ((lane >> 3) & 1) * 8 + (lane & 7);
    const int choff  = lane >> 4;
    const int tbase  = (LB + soff * 16 + wn * 8) * 32 + lane;

    uint32_t ah0[2][4], ah1[2][4];
    ldA1(smb, wm, rowoff, choff, 0, ah0);

    uint4 bq[2][2];
    bq[0][0] = __ldg(&g_B[tbase]);
    bq[0][1] = __ldg(&g_B[tbase + 32]);

#pragma unroll
    for (int g = 0; g < 32; ++g) {
        const int s = g >> 2, q = g & 3, cur = g & 1;
        if (g < 31) {
            const int ng = g + 1;
            const int tb = tbase + (ng >> 2) * 512 + (ng & 3) * 64;
            bq[cur ^ 1][0] = __ldg(&g_B[tb]);
            bq[cur ^ 1][1] = __ldg(&g_B[tb + 32]);
        }
        if (q == 3 && s < 7) {
            if (s & 1) ldA1(smb, wm, rowoff, choff, s + 1, ah0);
            else       ldA1(smb, wm, rowoff, choff, s + 1, ah1);
        }
        uint32_t (*ahc)[4] = (s & 1) ? ah1 : ah0;
#pragma unroll
        for (int mi = 0; mi < 2; ++mi)
#pragma unroll
            for (int f = 0; f < 2; ++f) {
                float* c = C[mi][q * 2 + f];
                mmah(c, ahc[mi], bq[cur][f].x, bq[cur][f].y);
                mmah(c, ahc[mi], bq[cur][f].z, bq[cur][f].w);
            }
    }
}

// edge chunk: k-step-paired B, ring depth-2 B prefetch, A double-buffered.
// Per-accumulator order unchanged (even k-step then odd) -> identical numerics.
__device__ __forceinline__ void mma_chunk_e(float C[2][8][4], uint32_t smb,
                                            int chunk, int lane, int wm, int wn) {
    const int rowoff = ((lane >> 3) & 1) * 8 + (lane & 7);
    const int choff  = lane >> 4;
    const int tbase  = (chunk * 64 + wn * 8) * 32 + lane;   // sp stride 512, nt stride 32

    uint32_t ahE[2][2][4], ahO[2][2][4];    // [buf][mi][4]
    ldA1(smb, wm, rowoff, choff, 0, ahE[0]);
    ldA1(smb, wm, rowoff, choff, 1, ahO[0]);

    uint4 b0 = __ldg(&g_Be[tbase]);
    uint4 b1 = __ldg(&g_Be[tbase + 32]);

#pragma unroll
    for (int it = 0; it < 32; ++it) {
        const int nt = it & 7, sp = it >> 3, buf = sp & 1;
        uint4 cur = (it & 1) ? b1 : b0;
        if (it < 30) {                       // B prefetch at distance 2
            const int n2 = it + 2;
            uint4 nb = __ldg(&g_Be[tbase + (n2 >> 3) * 512 + (n2 & 7) * 32]);
            if (it & 1) b1 = nb; else b0 = nb;
        }
        // dependent accumulate pairs split: C0E, C1E, C0O, C1O
        mmah(C[0][nt], ahE[buf][0], cur.x, cur.y);
        mmah(C[1][nt], ahE[buf][1], cur.x, cur.y);
        mmah(C[0][nt], ahO[buf][0], cur.z, cur.w);
        mmah(C[1][nt], ahO[buf][1], cur.z, cur.w);
        if (nt == 4 && sp < 3) {             // A prefetch into alternate buffer
            ldA1(smb, wm, rowoff, choff, 2 * (sp + 1),     ahE[buf ^ 1]);
            ldA1(smb, wm, rowoff, choff, 2 * (sp + 1) + 1, ahO[buf ^ 1]);
        }
    }
}

// bias + ReLU -> rewrite A smem; zero C. nt-outer: bias loaded once per nt.
__device__ __forceinline__ void epi_relu(float C[2][8][4], char* sm,
                                         const float* __restrict__ bias,
                                         int lane, int wm, int wn) {
    const int grp = lane >> 2, tig = lane & 3;
#pragma unroll
    for (int nt = 0; nt < 8; ++nt) {
        int col0 = wn * 64 + nt * 8 + tig * 2;
        float b0 = __ldg(bias + col0), b1 = __ldg(bias + col0 + 1);
#pragma unroll
        for (int mi = 0; mi < 2; ++mi) {
            int row = wm * 32 + mi * 16 + grp;
            float v0 = fmaxf(C[mi][nt][0] + b0, 0.f);
            float v1 = fmaxf(C[mi][nt][1] + b1, 0.f);
            float v2 = fmaxf(C[mi][nt][2] + b0, 0.f);
            float v3 = fmaxf(C[mi][nt][3] + b1, 0.f);
            *reinterpret_cast<uint32_t*>(sm + AH_OFF + row * STRB + col0 * 2) = packh2(v0, v1);
            *reinterpret_cast<uint32_t*>(sm + AH_OFF + (row + 8) * STRB + col0 * 2) = packh2(v2, v3);
            C[mi][nt][0] = C[mi][nt][1] = C[mi][nt][2] = C[mi][nt][3] = 0.f;
        }
    }
}

// add bias in place, per-row LN stats (64 rows, 2 wn partials). nt-outer.
__device__ __forceinline__ void ln_stats(float C[2][8][4], char* sm,
                                         const float* __restrict__ bias,
                                         int t, int lane, int wm, int wn,
                                         float mu[2][2], float rs[2][2]) {
    const int grp = lane >> 2, tig = lane & 3;
    float s[2][2] = {{0.f, 0.f}, {0.f, 0.f}};
    float q[2][2] = {{0.f, 0.f}, {0.f, 0.f}};
#pragma unroll
    for (int nt = 0; nt < 8; ++nt) {
        int col0 = wn * 64 + nt * 8 + tig * 2;
        float b0 = __ldg(bias + col0), b1 = __ldg(bias + col0 + 1);
#pragma unroll
        for (int mi = 0; mi < 2; ++mi) {
            C[mi][nt][0] += b0; C[mi][nt][1] += b1;
            C[mi][nt][2] += b0; C[mi][nt][3] += b1;
            s[mi][0] += C[mi][nt][0] + C[mi][nt][1];
            q[mi][0] += C[mi][nt][0] * C[mi][nt][0] + C[mi][nt][1] * C[mi][nt][1];
            s[mi][1] += C[mi][nt][2] + C[mi][nt][3];
            q[mi][1] += C[mi][nt][2] * C[mi][nt][2] + C[mi][nt][3] * C[mi][nt][3];
        }
    }
#pragma unroll
    for (int off = 1; off <= 2; off <<= 1)
#pragma unroll
        for (int mi = 0; mi < 2; ++mi)
#pragma unroll
            for (int h = 0; h < 2; ++h) {
                s[mi][h] += __shfl_xor_sync(0xffffffffu, s[mi][h], off);
                q[mi][h] += __shfl_xor_sync(0xffffffffu, q[mi][h], off);
            }
    float* ps = reinterpret_cast<float*>(sm + PS_OFF);
    float* pq = reinterpret_cast<float*>(sm + PQ_OFF);
    if (tig == 0) {
#pragma unroll
        for (int mi = 0; mi < 2; ++mi)
#pragma unroll
            for (int h = 0; h < 2; ++h) {
                int row = wm * 32 + mi * 16 + grp + h * 8;
                ps[wn * 64 + row] = s[mi][h];
                pq[wn * 64 + row] = q[mi][h];
            }
    }
    __syncthreads();
    float* smu = reinterpret_cast<float*>(sm + MU_OFF);
    float* srs = reinterpret_cast<float*>(sm + RS_OFF);
    if (t < 64) {
        float su = ps[t] + ps[64 + t];
        float sq = pq[t] + pq[64 + t];
        float m  = su * (1.f / 128.f);
        float v  = sq * (1.f / 128.f) - m * m;
        smu[t] = m;
        srs[t] = rsqrtf(v + 1e-5f);
    }
    __syncthreads();
#pragma unroll
    for (int mi = 0; mi < 2; ++mi)
#pragma unroll
        for (int h = 0; h < 2; ++h) {
            int row = wm * 32 + mi * 16 + grp + h * 8;
            mu[mi][h] = smu[row];
            rs[mi][h] = srs[row];
        }
}

// ============================ prep ==========================================
__device__ __forceinline__ void prep_one(const float* __restrict__ W, int idx, int tileBase) {
    int k = idx >> 7, n = idx & 127;
    float wv = W[idx];
    __half h = __float2half_rn(wv);
    __half l = __float2half_rn(wv - __half2float(h));
    int klocal = k & 15;
    int tile = tileBase + (k >> 4) * 16 + (n >> 3);
    int lane = (n & 7) * 4 + ((klocal >> 1) & 3);
    int reg  = (klocal >> 3) & 1;
    int half = klocal & 1;
    unsigned short* gb = reinterpret_cast<unsigned short*>(g_B);
    int base = (tile * 32 + lane) * 8;
    gb[base + reg * 2 + half]     = *reinterpret_cast<unsigned short*>(&h);
    gb[base + 4 + reg * 2 + half] = *reinterpret_cast<unsigned short*>(&l);
}

__device__ __forceinline__ void prep_one_e(const float* __restrict__ W, int li,
                                           int chunk, int koff) {
    int k = li >> 7, n = li & 127;
    float wv = W[(k + koff) * 128 + n];
    __half h = __float2half_rn(wv);
    int s = k >> 4, klocal = k & 15;
    int sp = s >> 1, par = s & 1;
    int lane = (n & 7) * 4 + ((klocal >> 1) & 3);
    int reg  = (klocal >> 3) & 1;
    int half = klocal & 1;
    unsigned short* gb = reinterpret_cast<unsigned short*>(g_Be);
    int base = ((chunk * 64 + sp * 16 + (n >> 3)) * 32 + lane) * 8;
    gb[base + par * 4 + reg * 2 + half] = *reinterpret_cast<unsigned short*>(&h);
}

__global__ void prep_all(const float* __restrict__ eW0, const float* __restrict__ eW1,
                         const float* __restrict__ eW2, const float* __restrict__ nW0,
                         const float* __restrict__ nW1, const float* __restrict__ nW2) {
    int idx = blockIdx.x * 256 + threadIdx.x;    // grid covers 180224
    if (idx < 32768) { prep_one(eW0, idx, TB_EW0); return; }
    if (idx < 81920) {
        int r = idx - 32768;
        int li = r & 16383;
        switch (r >> 14) {
            case 0: prep_one(nW0, li, TB_NW0); break;
            case 1: prep_one(nW1, li, TB_NW1); break;
            default: prep_one(nW2, li, TB_NW2); break;
        }
        return;
    }
    {
        int r = idx - 81920;
        int li = r & 16383;
        switch (r >> 14) {
            case 0: prep_one_e(eW0, li, 0, 256); break;
            case 1: prep_one_e(eW1, li, 1, 0);   break;
            default: prep_one_e(eW2, li, 2, 0);  break;
        }
    }
}

// ============================ kernels =======================================
__global__ void __launch_bounds__(128, 4)
mpnn_pre(const float* __restrict__ x, int natoms) {
    extern __shared__ char sm[];
    const uint32_t smb = smem_u32(sm);
    const int t = threadIdx.x, lane = t & 31, w = t >> 5;
    const int wm = w & 1, wn = w >> 1;
    const long r0 = (long)blockIdx.x * 64;
    const int lr = t >> 1, half = t & 1;
    const int grp = lane >> 2, tig = lane & 3;

    {
        bool valid = (r0 + lr) < natoms;
        const float* src = x + (r0 + lr) * 128 + half * 64;
#pragma unroll
        for (int q2 = 0; q2 < 16; ++q2) {
            float4 v = valid ? *reinterpret_cast<const float4*>(src + q2 * 4)
                             : make_float4(0.f, 0.f, 0.f, 0.f);
            uint2 hp;
            hp.x = packh2(v.x, v.y);
            hp.y = packh2(v.z, v.w);
            int off = lr * STRB + (half * 64 + q2 * 4) * 2;
            *reinterpret_cast<uint2*>(sm + AH_OFF + off) = hp;
        }
    }
    __syncthreads();

    float C[2][8][4];
#pragma unroll 1
    for (int pass = 0; pass < 2; ++pass) {
#pragma unroll
        for (int mi = 0; mi < 2; ++mi)
#pragma unroll
            for (int nt = 0; nt < 8; ++nt)
#pragma unroll
                for (int e = 0; e < 4; ++e) C[mi][nt][e] = 0.f;
        mma_layer(C, smb, TB_EW0, pass * 8, lane, wm, wn);
        float* dst = pass ? g_Q : g_P;
#pragma unroll
        for (int mi = 0; mi < 2; ++mi)
#pragma unroll
            for (int h = 0; h < 2; ++h) {
                int row = wm * 32 + mi * 16 + grp + h * 8;
                if (r0 + row < natoms) {
#pragma unroll
                    for (int nt = 0; nt < 8; ++nt) {
                        int col0 = wn * 64 + nt * 8 + tig * 2;
                        float2 o = {C[mi][nt][h * 2 + 0], C[mi][nt][h * 2 + 1]};
                        *reinterpret_cast<float2*>(dst + (r0 + row) * 128 + col0) = o;
                    }
                }
            }
    }
}

__global__ void __launch_bounds__(128, 4)
mpnn_edge(const float* __restrict__ eattr,
          const int* __restrict__ recv, const int* __restrict__ send,
          const float* __restrict__ eb0, const float* __restrict__ eb1,
          const float* __restrict__ eb2, const float* __restrict__ eg,
          const float* __restrict__ ebeta) {
    extern __shared__ char sm[];
    const uint32_t smb = smem_u32(sm);
    const int t = threadIdx.x, lane = t & 31, w = t >> 5;
    const int wm = w & 1, wn = w >> 1;
    const long e0 = (long)blockIdx.x * 64;
    const int lr = t >> 1, half = t & 1;
    const int grp = lane >> 2, tig = lane & 3;

    stageA(sm, eattr + (e0 + lr) * 128 + half * 64, lr, half * 64);

    float C[2][8][4];
#pragma unroll
    for (int mi = 0; mi < 2; ++mi)
#pragma unroll
        for (int h = 0; h < 2; ++h) {
            int row = wm * 32 + mi * 16 + grp + h * 8;
            long er = e0 + row;
            const float* prow = g_P + (long)__ldg(recv + er) * 128;
            const float* qrow = g_Q + (long)__ldg(send + er) * 128;
#pragma unroll
            for (int nt = 0; nt < 8; ++nt) {
                int col0 = wn * 64 + nt * 8 + tig * 2;
                float2 p = *reinterpret_cast<const float2*>(prow + col0);
                float2 q = *reinterpret_cast<const float2*>(qrow + col0);
                C[mi][nt][h * 2 + 0] = p.x + q.x;
                C[mi][nt][h * 2 + 1] = p.y + q.y;
            }
        }
    __syncthreads();

    mma_chunk_e(C, smb, 0, lane, wm, wn);   // + e @ W0c
    __syncthreads();
    epi_relu(C, sm, eb0, lane, wm, wn);
    __syncthreads();
    mma_chunk_e(C, smb, 1, lane, wm, wn);   // layer 1
    __syncthreads();
    epi_relu(C, sm, eb1, lane, wm, wn);
    __syncthreads();
    mma_chunk_e(C, smb, 2, lane, wm, wn);   // layer 2

    float mu[2][2], rs[2][2];
    ln_stats(C, sm, eb2, t, lane, wm, wn, mu, rs);

    // LN-apply + block-local K=16 aggregation. nt-outer: eg/ebeta once per nt.
    float part[2][2][4];
#pragma unroll
    for (int mi = 0; mi < 2; ++mi)
#pragma unroll
        for (int h = 0; h < 2; ++h)
#pragma unroll
            for (int g = 0; g < 4; ++g) part[mi][h][g] = 0.f;
#pragma unroll
    for (int nt = 0; nt < 8; ++nt) {
        int col0 = wn * 64 + nt * 8 + tig * 2;
        float g0 = __ldg(eg + col0),    g1 = __ldg(eg + col0 + 1);
        float b0 = __ldg(ebeta + col0), b1 = __ldg(ebeta + col0 + 1);
        int g = nt >> 1;
#pragma unroll
        for (int mi = 0; mi < 2; ++mi)
#pragma unroll
            for (int h = 0; h < 2; ++h)
                part[mi][h][g] += (C[mi][nt][h * 2 + 0] - mu[mi][h]) * rs[mi][h] * g0 + b0
                                + (C[mi][nt][h * 2 + 1] - mu[mi][h]) * rs[mi][h] * g1 + b1;
    }
#pragma unroll
    for (int mi = 0; mi < 2; ++mi)
#pragma unroll
        for (int h = 0; h < 2; ++h) {
#pragma unroll
            for (int g = 0; g < 4; ++g) {
                part[mi][h][g] += __shfl_xor_sync(0xffffffffu, part[mi][h][g], 1);
                part[mi][h][g] += __shfl_xor_sync(0xffffffffu, part[mi][h][g], 2);
            }
            int row = wm * 32 + mi * 16 + grp + h * 8;
            int i   = (row & 15) * 8 + wn * 4 + tig;
            g_nodein[((e0 >> 4) + (row >> 4)) * 128 + i] = part[mi][h][tig];
        }
}

__global__ void __launch_bounds__(128, 4)
mpnn_node(const float* __restrict__ nb0, const float* __restrict__ nb1,
          const float* __restrict__ nb2, const float* __restrict__ ng,
          const float* __restrict__ nbeta, float* __restrict__ out, int natoms) {
    extern __shared__ char sm[];
    const uint32_t smb = smem_u32(sm);
    const int t = threadIdx.x, lane = t & 31, w = t >> 5;
    const int wm = w & 1, wn = w >> 1;
    const long r0 = (long)blockIdx.x * 64;
    const int lr = t >> 1, half = t & 1;

    {
        bool valid = (r0 + lr) < natoms;
        const float* src = g_nodein + (r0 + lr) * 128 + half * 64;
#pragma unroll
        for (int q2 = 0; q2 < 16; ++q2) {
            float4 v = valid ? *reinterpret_cast<const float4*>(src + q2 * 4)
                             : make_float4(0.f, 0.f, 0.f, 0.f);
            uint2 hp;
            hp.x = packh2(v.x, v.y);
            hp.y = packh2(v.z, v.w);
            int off = lr * STRB + (half * 64 + q2 * 4) * 2;
            *reinterpret_cast<uint2*>(sm + AH_OFF + off) = hp;
        }
    }
    __syncthreads();

    float C[2][8][4];
#pragma unroll
    for (int mi = 0; mi < 2; ++mi)
#pragma unroll
        for (int nt = 0; nt < 8; ++nt)
#pragma unroll
            for (int e = 0; e < 4; ++e) C[mi][nt][e] = 0.f;

    mma_layer(C, smb, TB_NW0, 0, lane, wm, wn);
    __syncthreads();
    epi_relu(C, sm, nb0, lane, wm, wn);
    __syncthreads();
    mma_layer(C, smb, TB_NW1, 0, lane, wm, wn);
    __syncthreads();
    epi_relu(C, sm, nb1, lane, wm, wn);
    __syncthreads();
    mma_layer(C, smb, TB_NW2, 0, lane, wm, wn);

    float mu[2][2], rs[2][2];
    ln_stats(C, sm, nb2, t, lane, wm, wn, mu, rs);

    const int grp = lane >> 2, tig = lane & 3;
#pragma unroll
    for (int nt = 0; nt < 8; ++nt) {
        int col0 = wn * 64 + nt * 8 + tig * 2;
        float g0 = __ldg(ng + col0),     g1 = __ldg(ng + col0 + 1);
        float be0 = __ldg(nbeta + col0), be1 = __ldg(nbeta + col0 + 1);
#pragma unroll
        for (int mi = 0; mi < 2; ++mi) {
            int r1 = wm * 32 + mi * 16 + grp;
            if (r0 + r1 < natoms) {
                float2 o1 = {(C[mi][nt][0] - mu[mi][0]) * rs[mi][0] * g0 + be0,
                             (C[mi][nt][1] - mu[mi][0]) * rs[mi][0] * g1 + be1};
                *reinterpret_cast<float2*>(out + (r0 + r1) * 128 + col0) = o1;
            }
            if (r0 + r1 + 8 < natoms) {
                float2 o2 = {(C[mi][nt][2] - mu[mi][1]) * rs[mi][1] * g0 + be0,
                             (C[mi][nt][3] - mu[mi][1]) * rs[mi][1] * g1 + be1};
                *reinterpret_cast<float2*>(out + (r0 + r1 + 8) * 128 + col0) = o2;
            }
        }
    }
}

// ============================ launch ========================================
extern "C" void kernel_launch(void* const* d_in, const int* in_sizes, int n_in,
                              void* d_out, int out_size) {
    const float* x         = (const float*)d_in[0];
    const float* edge_attr = (const float*)d_in[1];
    const int*   receivers = (const int*)d_in[2];
    const int*   senders   = (const int*)d_in[3];

    int wi = 4;
    while (wi < n_in && in_sizes[wi] != 3 * 128 * 128) wi++;
    if (wi >= n_in) wi = (in_sizes[4] == 1) ? 5 : 4;

    const float* eW0   = (const float*)d_in[wi + 0];
    const float* eb0   = (const float*)d_in[wi + 1];
    const float* eW1   = (const float*)d_in[wi + 2];
    const float* eb1   = (const float*)d_in[wi + 3];
    const float* eW2   = (const float*)d_in[wi + 4];
    const float* eb2   = (const float*)d_in[wi + 5];
    const float* eg    = (const float*)d_in[wi + 6];
    const float* ebeta = (const float*)d_in[wi + 7];
    const float* nW0   = (const float*)d_in[wi + 8];
    const float* nb0   = (const float*)d_in[wi + 9];
    const float* nW1   = (const float*)d_in[wi + 10];
    const float* nb1   = (const float*)d_in[wi + 11];
    const float* nW2   = (const float*)d_in[wi + 12];
    const float* nb2   = (const float*)d_in[wi + 13];
    const float* ng    = (const float*)d_in[wi + 14];
    const float* nbeta = (const float*)d_in[wi + 15];

    int E      = in_sizes[2];
    int natoms = out_size / 128;
    int nblk   = (natoms + 63) / 64;

    prep_all<<<704, 256>>>(eW0, eW1, eW2, nW0, nW1, nW2);
    mpnn_pre<<<nblk, 128, SMEM_TOTAL>>>(x, natoms);
    mpnn_edge<<<E / 64, 128, SMEM_TOTAL>>>(edge_attr, receivers, senders,
                                           eb0, eb1, eb2, eg, ebeta);
    mpnn_node<<<nblk, 128, SMEM_TOTAL>>>(nb0, nb1, nb2, ng, nbeta,
                                         (float*)d_out, natoms);
}

// round 15
// speedup vs baseline: 1.7965x; 1.0071x over previous
#include <cuda_runtime.h>
#include <cuda_fp16.h>
#include <cstdint>

// ============================================================================
// MPNN on sm_103 via warp-level mma.sync m16n8k16 fp16. (R14 structure:
// 64 rows / 128 threads per CTA; k-pair-packed edge B; depth-2 pipelines.)
// pre/node layers: 2-pass split-B (A·Bh + A·Bl), f32 accumulate, depth-2.
// edge layers: single-pass A·Bh, B ring depth-2 + A double-buffer pipeline.
// Edge layer-0 factorization: [x_r|x_s|e]@W0 = P[recv] + Q[send] + e@W0c.
// prep: one thread per output uint4 fragment (coalesced STG.128).
// ============================================================================

#define STRB 272
#define AH_OFF 0
#define PS_OFF 17408
#define PQ_OFF 17920
#define MU_OFF 18432
#define RS_OFF 18688
#define SMEM_TOTAL 18944

__device__ __align__(16) uint4 g_B[1024 * 32];    // 2-pass fragments (pre/node)
__device__ __align__(16) uint4 g_Be[3 * 64 * 32]; // edge: k-pair-packed Bh
__device__ float g_nodein[20000 * 128];
__device__ float g_P[20000 * 128];
__device__ float g_Q[20000 * 128];

#define TB_EW0 0
#define TB_NW0 640
#define TB_NW1 768
#define TB_NW2 896

// ============================ helpers =======================================
__device__ __forceinline__ uint32_t smem_u32(const void* p) {
    uint32_t a;
    asm("{ .reg .u64 t; cvta.to.shared.u64 t, %1; cvt.u32.u64 %0, t; }" : "=r"(a) : "l"(p));
    return a;
}

__device__ __forceinline__ void ldmA(uint32_t addr, uint32_t a[4]) {
    asm volatile("ldmatrix.sync.aligned.m8n8.x4.shared.b16 {%0,%1,%2,%3}, [%4];"
                 : "=r"(a[0]), "=r"(a[1]), "=r"(a[2]), "=r"(a[3]) : "r"(addr));
}

__device__ __forceinline__ void mmah(float* c, const uint32_t a[4], uint32_t b0, uint32_t b1) {
    asm volatile(
        "mma.sync.aligned.m16n8k16.row.col.f32.f16.f16.f32 "
        "{%0,%1,%2,%3}, {%4,%5,%6,%7}, {%8,%9}, {%0,%1,%2,%3};"
        : "+f"(c[0]), "+f"(c[1]), "+f"(c[2]), "+f"(c[3])
        : "r"(a[0]), "r"(a[1]), "r"(a[2]), "r"(a[3]), "r"(b0), "r"(b1));
}

__device__ __forceinline__ uint32_t packh2(float a, float b) {
    __half2 h = __floats2half2_rn(a, b);
    return *reinterpret_cast<uint32_t*>(&h);
}

__device__ __forceinline__ uint32_t packhh(__half a, __half b) {
    __half2 h; h.x = a; h.y = b;
    return *reinterpret_cast<uint32_t*>(&h);
}

// stage 64 cols of one row into A smem (fp16)
__device__ __forceinline__ void stageA(char* sm, const float* __restrict__ src,
                                       int lr, int colbase) {
#pragma unroll
    for (int q = 0; q < 16; ++q) {
        float4 v = *reinterpret_cast<const float4*>(src + q * 4);
        uint2 hp;
        hp.x = packh2(v.x, v.y);
        hp.y = packh2(v.z, v.w);
        int off = lr * STRB + (colbase + q * 4) * 2;
        *reinterpret_cast<uint2*>(sm + AH_OFF + off) = hp;
    }
}

__device__ __forceinline__ void ldA1(uint32_t smb, int wm, int rowoff, int choff, int s,
                                     uint32_t ah[2][4]) {
#pragma unroll
    for (int mi = 0; mi < 2; ++mi) {
        uint32_t base = smb + (uint32_t)((wm * 32 + mi * 16 + rowoff) * STRB
                                         + (s * 2 + choff) * 16);
        ldmA(base + AH_OFF, ah[mi]);
    }
}

// 2-pass chunk (A·Bh + A·Bl): B prefetch distance-2 quarters, split pairs.
// Per-accumulator order unchanged (Bh then Bl, s-increasing).
__device__ __forceinline__ void mma_layer(float C[2][8][4], uint32_t smb,
                                          int LB, int soff, int lane, int wm, int wn) {
    const int rowoff = ((lane >> 3) & 1) * 8 + (lane & 7);
    const int choff  = lane >> 4;
    const int tbase  = (LB + soff * 16 + wn * 8) * 32 + lane;

    uint32_t ah0[2][4], ah1[2][4];
    ldA1(smb, wm, rowoff, choff, 0, ah0);

    uint4 bqA[2], bqB[2];
    bqA[0] = __ldg(&g_B[tbase]);
    bqA[1] = __ldg(&g_B[tbase + 32]);
    bqB[0] = __ldg(&g_B[tbase + 64]);
    bqB[1] = __ldg(&g_B[tbase + 96]);

#pragma unroll
    for (int g = 0; g < 32; ++g) {
        const int s = g >> 2, q = g & 3;
        uint4 c0 = (g & 1) ? bqB[0] : bqA[0];
        uint4 c1 = (g & 1) ? bqB[1] : bqA[1];
        if (g < 30) {                        // distance-2 prefetch
            const int ng = g + 2;
            const int tb = tbase + (ng >> 2) * 512 + (ng & 3) * 64;
            if (g & 1) { bqB[0] = __ldg(&g_B[tb]); bqB[1] = __ldg(&g_B[tb + 32]); }
            else       { bqA[0] = __ldg(&g_B[tb]); bqA[1] = __ldg(&g_B[tb + 32]); }
        }
        if (q == 3 && s < 7) {
            if (s & 1) ldA1(smb, wm, rowoff, choff, s + 1, ah0);
            else       ldA1(smb, wm, rowoff, choff, s + 1, ah1);
        }
        uint32_t (*ahc)[4] = (s & 1) ? ah1 : ah0;
        mmah(C[0][q * 2 + 0], ahc[0], c0.x, c0.y);
        mmah(C[1][q * 2 + 0], ahc[1], c0.x, c0.y);
        mmah(C[0][q * 2 + 1], ahc[0], c1.x, c1.y);
        mmah(C[1][q * 2 + 1], ahc[1], c1.x, c1.y);
        mmah(C[0][q * 2 + 0], ahc[0], c0.z, c0.w);
        mmah(C[1][q * 2 + 0], ahc[1], c0.z, c0.w);
        mmah(C[0][q * 2 + 1], ahc[0], c1.z, c1.w);
        mmah(C[1][q * 2 + 1], ahc[1], c1.z, c1.w);
    }
}

// edge chunk: k-step-paired B, ring depth-2 B prefetch, A double-buffered.
__device__ __forceinline__ void mma_chunk_e(float C[2][8][4], uint32_t smb,
                                            int chunk, int lane, int wm, int wn) {
    const int rowoff = ((lane >> 3) & 1) * 8 + (lane & 7);
    const int choff  = lane >> 4;
    const int tbase  = (chunk * 64 + wn * 8) * 32 + lane;

    uint32_t ahE[2][2][4], ahO[2][2][4];
    ldA1(smb, wm, rowoff, choff, 0, ahE[0]);
    ldA1(smb, wm, rowoff, choff, 1, ahO[0]);

    uint4 b0 = __ldg(&g_Be[tbase]);
    uint4 b1 = __ldg(&g_Be[tbase + 32]);

#pragma unroll
    for (int it = 0; it < 32; ++it) {
        const int nt = it & 7, sp = it >> 3, buf = sp & 1;
        uint4 cur = (it & 1) ? b1 : b0;
        if (it < 30) {
            const int n2 = it + 2;
            uint4 nb = __ldg(&g_Be[tbase + (n2 >> 3) * 512 + (n2 & 7) * 32]);
            if (it & 1) b1 = nb; else b0 = nb;
        }
        mmah(C[0][nt], ahE[buf][0], cur.x, cur.y);
        mmah(C[1][nt], ahE[buf][1], cur.x, cur.y);
        mmah(C[0][nt], ahO[buf][0], cur.z, cur.w);
        mmah(C[1][nt], ahO[buf][1], cur.z, cur.w);
        if (nt == 4 && sp < 3) {
            ldA1(smb, wm, rowoff, choff, 2 * (sp + 1),     ahE[buf ^ 1]);
            ldA1(smb, wm, rowoff, choff, 2 * (sp + 1) + 1, ahO[buf ^ 1]);
        }
    }
}

// bias + ReLU -> rewrite A smem; zero C. nt-outer.
__device__ __forceinline__ void epi_relu(float C[2][8][4], char* sm,
                                         const float* __restrict__ bias,
                                         int lane, int wm, int wn) {
    const int grp = lane >> 2, tig = lane & 3;
#pragma unroll
    for (int nt = 0; nt < 8; ++nt) {
        int col0 = wn * 64 + nt * 8 + tig * 2;
        float b0 = __ldg(bias + col0), b1 = __ldg(bias + col0 + 1);
#pragma unroll
        for (int mi = 0; mi < 2; ++mi) {
            int row = wm * 32 + mi * 16 + grp;
            float v0 = fmaxf(C[mi][nt][0] + b0, 0.f);
            float v1 = fmaxf(C[mi][nt][1] + b1, 0.f);
            float v2 = fmaxf(C[mi][nt][2] + b0, 0.f);
            float v3 = fmaxf(C[mi][nt][3] + b1, 0.f);
            *reinterpret_cast<uint32_t*>(sm + AH_OFF + row * STRB + col0 * 2) = packh2(v0, v1);
            *reinterpret_cast<uint32_t*>(sm + AH_OFF + (row + 8) * STRB + col0 * 2) = packh2(v2, v3);
            C[mi][nt][0] = C[mi][nt][1] = C[mi][nt][2] = C[mi][nt][3] = 0.f;
        }
    }
}

// add bias in place, per-row LN stats. nt-outer.
__device__ __forceinline__ void ln_stats(float C[2][8][4], char* sm,
                                         const float* __restrict__ bias,
                                         int t, int lane, int wm, int wn,
                                         float mu[2][2], float rs[2][2]) {
    const int grp = lane >> 2, tig = lane & 3;
    float s[2][2] = {{0.f, 0.f}, {0.f, 0.f}};
    float q[2][2] = {{0.f, 0.f}, {0.f, 0.f}};
#pragma unroll
    for (int nt = 0; nt < 8; ++nt) {
        int col0 = wn * 64 + nt * 8 + tig * 2;
        float b0 = __ldg(bias + col0), b1 = __ldg(bias + col0 + 1);
#pragma unroll
        for (int mi = 0; mi < 2; ++mi) {
            C[mi][nt][0] += b0; C[mi][nt][1] += b1;
            C[mi][nt][2] += b0; C[mi][nt][3] += b1;
            s[mi][0] += C[mi][nt][0] + C[mi][nt][1];
            q[mi][0] += C[mi][nt][0] * C[mi][nt][0] + C[mi][nt][1] * C[mi][nt][1];
            s[mi][1] += C[mi][nt][2] + C[mi][nt][3];
            q[mi][1] += C[mi][nt][2] * C[mi][nt][2] + C[mi][nt][3] * C[mi][nt][3];
        }
    }
#pragma unroll
    for (int off = 1; off <= 2; off <<= 1)
#pragma unroll
        for (int mi = 0; mi < 2; ++mi)
#pragma unroll
            for (int h = 0; h < 2; ++h) {
                s[mi][h] += __shfl_xor_sync(0xffffffffu, s[mi][h], off);
                q[mi][h] += __shfl_xor_sync(0xffffffffu, q[mi][h], off);
            }
    float* ps = reinterpret_cast<float*>(sm + PS_OFF);
    float* pq = reinterpret_cast<float*>(sm + PQ_OFF);
    if (tig == 0) {
#pragma unroll
        for (int mi = 0; mi < 2; ++mi)
#pragma unroll
            for (int h = 0; h < 2; ++h) {
                int row = wm * 32 + mi * 16 + grp + h * 8;
                ps[wn * 64 + row] = s[mi][h];
                pq[wn * 64 + row] = q[mi][h];
            }
    }
    __syncthreads();
    float* smu = reinterpret_cast<float*>(sm + MU_OFF);
    float* srs = reinterpret_cast<float*>(sm + RS_OFF);
    if (t < 64) {
        float su = ps[t] + ps[64 + t];
        float sq = pq[t] + pq[64 + t];
        float m  = su * (1.f / 128.f);
        float v  = sq * (1.f / 128.f) - m * m;
        smu[t] = m;
        srs[t] = rsqrtf(v + 1e-5f);
    }
    __syncthreads();
#pragma unroll
    for (int mi = 0; mi < 2; ++mi)
#pragma unroll
        for (int h = 0; h < 2; ++h) {
            int row = wm * 32 + mi * 16 + grp + h * 8;
            mu[mi][h] = smu[row];
            rs[mi][h] = srs[row];
        }
}

// ============================ prep ==========================================
// One thread per output uint4 fragment: coalesced STG.128, 4-8 LDG each.
__device__ __forceinline__ void prep_b_frag(const float* __restrict__ W,
                                            int tileoff, int dstTile, int lane) {
    int n  = (tileoff & 15) * 8 + (lane >> 2);
    int k0 = (tileoff >> 4) * 16 + (lane & 3) * 2;
    float w00 = W[(k0)     * 128 + n], w01 = W[(k0 + 1) * 128 + n];
    float w10 = W[(k0 + 8) * 128 + n], w11 = W[(k0 + 9) * 128 + n];
    __half h00 = __float2half_rn(w00), h01 = __float2half_rn(w01);
    __half h10 = __float2half_rn(w10), h11 = __float2half_rn(w11);
    __half l00 = __float2half_rn(w00 - __half2float(h00));
    __half l01 = __float2half_rn(w01 - __half2float(h01));
    __half l10 = __float2half_rn(w10 - __half2float(h10));
    __half l11 = __float2half_rn(w11 - __half2float(h11));
    uint4 v;
    v.x = packhh(h00, h01); v.y = packhh(h10, h11);
    v.z = packhh(l00, l01); v.w = packhh(l10, l11);
    g_B[dstTile * 32 + lane] = v;
}

__device__ __forceinline__ void prep_be_frag(const float* __restrict__ W,
                                             int tileoff, int img, int koff, int lane) {
    int n  = (tileoff & 15) * 8 + (lane >> 2);
    int kA = (tileoff >> 4) * 32 + (lane & 3) * 2 + koff;
    __half h[8];
#pragma unroll
    for (int j = 0; j < 4; ++j) {
        h[2 * j]     = __float2half_rn(W[(kA + j * 8)     * 128 + n]);
        h[2 * j + 1] = __float2half_rn(W[(kA + j * 8 + 1) * 128 + n]);
    }
    uint4 v;
    v.x = packhh(h[0], h[1]); v.y = packhh(h[2], h[3]);
    v.z = packhh(h[4], h[5]); v.w = packhh(h[6], h[7]);
    g_Be[(img * 64 + tileoff) * 32 + lane] = v;
}

__global__ void prep_all(const float* __restrict__ eW0, const float* __restrict__ eW1,
                         const float* __restrict__ eW2, const float* __restrict__ nW0,
                         const float* __restrict__ nW1, const float* __restrict__ nW2) {
    int idx = blockIdx.x * 256 + threadIdx.x;    // grid covers 26624
    int lane = idx & 31, frag = idx >> 5;
    if (frag < 256)       { prep_b_frag(eW0, frag,        TB_EW0 + frag,        lane); return; }
    if (frag < 384)       { prep_b_frag(nW0, frag - 256,  TB_NW0 + frag - 256,  lane); return; }
    if (frag < 512)       { prep_b_frag(nW1, frag - 384,  TB_NW1 + frag - 384,  lane); return; }
    if (frag < 640)       { prep_b_frag(nW2, frag - 512,  TB_NW2 + frag - 512,  lane); return; }
    if (frag < 704)       { prep_be_frag(eW0, frag - 640, 0, 256, lane); return; }
    if (frag < 768)       { prep_be_frag(eW1, frag - 704, 1, 0,   lane); return; }
    if (frag < 832)       { prep_be_frag(eW2, frag - 768, 2, 0,   lane); return; }
}

// ============================ kernels =======================================
__global__ void __launch_bounds__(128, 4)
mpnn_pre(const float* __restrict__ x, int natoms) {
    extern __shared__ char sm[];
    const uint32_t smb = smem_u32(sm);
    const int t = threadIdx.x, lane = t & 31, w = t >> 5;
    const int wm = w & 1, wn = w >> 1;
    const long r0 = (long)blockIdx.x * 64;
    const int lr = t >> 1, half = t & 1;
    const int grp = lane >> 2, tig = lane & 3;

    {
        bool valid = (r0 + lr) < natoms;
        const float* src = x + (r0 + lr) * 128 + half * 64;
#pragma unroll
        for (int q2 = 0; q2 < 16; ++q2) {
            float4 v = valid ? *reinterpret_cast<const float4*>(src + q2 * 4)
                             : make_float4(0.f, 0.f, 0.f, 0.f);
            uint2 hp;
            hp.x = packh2(v.x, v.y);
            hp.y = packh2(v.z, v.w);
            int off = lr * STRB + (half * 64 + q2 * 4) * 2;
            *reinterpret_cast<uint2*>(sm + AH_OFF + off) = hp;
        }
    }
    __syncthreads();

    float C[2][8][4];
#pragma unroll 1
    for (int pass = 0; pass < 2; ++pass) {
#pragma unroll
        for (int mi = 0; mi < 2; ++mi)
#pragma unroll
            for (int nt = 0; nt < 8; ++nt)
#pragma unroll
                for (int e = 0; e < 4; ++e) C[mi][nt][e] = 0.f;
        mma_layer(C, smb, TB_EW0, pass * 8, lane, wm, wn);
        float* dst = pass ? g_Q : g_P;
#pragma unroll
        for (int mi = 0; mi < 2; ++mi)
#pragma unroll
            for (int h = 0; h < 2; ++h) {
                int row = wm * 32 + mi * 16 + grp + h * 8;
                if (r0 + row < natoms) {
#pragma unroll
                    for (int nt = 0; nt < 8; ++nt) {
                        int col0 = wn * 64 + nt * 8 + tig * 2;
                        float2 o = {C[mi][nt][h * 2 + 0], C[mi][nt][h * 2 + 1]};
                        *reinterpret_cast<float2*>(dst + (r0 + row) * 128 + col0) = o;
                    }
                }
            }
    }
}

__global__ void __launch_bounds__(128, 4)
mpnn_edge(const float* __restrict__ eattr,
          const int* __restrict__ recv, const int* __restrict__ send,
          const float* __restrict__ eb0, const float* __restrict__ eb1,
          const float* __restrict__ eb2, const float* __restrict__ eg,
          const float* __restrict__ ebeta) {
    extern __shared__ char sm[];
    const uint32_t smb = smem_u32(sm);
    const int t = threadIdx.x, lane = t & 31, w = t >> 5;
    const int wm = w & 1, wn = w >> 1;
    const long e0 = (long)blockIdx.x * 64;
    const int lr = t >> 1, half = t & 1;
    const int grp = lane >> 2, tig = lane & 3;

    stageA(sm, eattr + (e0 + lr) * 128 + half * 64, lr, half * 64);

    float C[2][8][4];
#pragma unroll
    for (int mi = 0; mi < 2; ++mi)
#pragma unroll
        for (int h = 0; h < 2; ++h) {
            int row = wm * 32 + mi * 16 + grp + h * 8;
            long er = e0 + row;
            const float* prow = g_P + (long)__ldg(recv + er) * 128;
            const float* qrow = g_Q + (long)__ldg(send + er) * 128;
#pragma unroll
            for (int nt = 0; nt < 8; ++nt) {
                int col0 = wn * 64 + nt * 8 + tig * 2;
                float2 p = *reinterpret_cast<const float2*>(prow + col0);
                float2 q = *reinterpret_cast<const float2*>(qrow + col0);
                C[mi][nt][h * 2 + 0] = p.x + q.x;
                C[mi][nt][h * 2 + 1] = p.y + q.y;
            }
        }
    __syncthreads();

    mma_chunk_e(C, smb, 0, lane, wm, wn);   // + e @ W0c
    __syncthreads();
    epi_relu(C, sm, eb0, lane, wm, wn);
    __syncthreads();
    mma_chunk_e(C, smb, 1, lane, wm, wn);   // layer 1
    __syncthreads();
    epi_relu(C, sm, eb1, lane, wm, wn);
    __syncthreads();
    mma_chunk_e(C, smb, 2, lane, wm, wn);   // layer 2

    float mu[2][2], rs[2][2];
    ln_stats(C, sm, eb2, t, lane, wm, wn, mu, rs);

    float part[2][2][4];
#pragma unroll
    for (int mi = 0; mi < 2; ++mi)
#pragma unroll
        for (int h = 0; h < 2; ++h)
#pragma unroll
            for (int g = 0; g < 4; ++g) part[mi][h][g] = 0.f;
#pragma unroll
    for (int nt = 0; nt < 8; ++nt) {
        int col0 = wn * 64 + nt * 8 + tig * 2;
        float g0 = __ldg(eg + col0),    g1 = __ldg(eg + col0 + 1);
        float b0 = __ldg(ebeta + col0), b1 = __ldg(ebeta + col0 + 1);
        int g = nt >> 1;
#pragma unroll
        for (int mi = 0; mi < 2; ++mi)
#pragma unroll
            for (int h = 0; h < 2; ++h)
                part[mi][h][g] += (C[mi][nt][h * 2 + 0] - mu[mi][h]) * rs[mi][h] * g0 + b0
                                + (C[mi][nt][h * 2 + 1] - mu[mi][h]) * rs[mi][h] * g1 + b1;
    }
#pragma unroll
    for (int mi = 0; mi < 2; ++mi)
#pragma unroll
        for (int h = 0; h < 2; ++h) {
#pragma unroll
            for (int g = 0; g < 4; ++g) {
                part[mi][h][g] += __shfl_xor_sync(0xffffffffu, part[mi][h][g], 1);
                part[mi][h][g] += __shfl_xor_sync(0xffffffffu, part[mi][h][g], 2);
            }
            int row = wm * 32 + mi * 16 + grp + h * 8;
            int i   = (row & 15) * 8 + wn * 4 + tig;
            g_nodein[((e0 >> 4) + (row >> 4)) * 128 + i] = part[mi][h][tig];
        }
}

__global__ void __launch_bounds__(128, 4)
mpnn_node(const float* __restrict__ nb0, const float* __restrict__ nb1,
          const float* __restrict__ nb2, const float* __restrict__ ng,
          const float* __restrict__ nbeta, float* __restrict__ out, int natoms) {
    extern __shared__ char sm[];
    const uint32_t smb = smem_u32(sm);
    const int t = threadIdx.x, lane = t & 31, w = t >> 5;
    const int wm = w & 1, wn = w >> 1;
    const long r0 = (long)blockIdx.x * 64;
    const int lr = t >> 1, half = t & 1;

    {
        bool valid = (r0 + lr) < natoms;
        const float* src = g_nodein + (r0 + lr) * 128 + half * 64;
#pragma unroll
        for (int q2 = 0; q2 < 16; ++q2) {
            float4 v = valid ? *reinterpret_cast<const float4*>(src + q2 * 4)
                             : make_float4(0.f, 0.f, 0.f, 0.f);
            uint2 hp;
            hp.x = packh2(v.x, v.y);
            hp.y = packh2(v.z, v.w);
            int off = lr * STRB + (half * 64 + q2 * 4) * 2;
            *reinterpret_cast<uint2*>(sm + AH_OFF + off) = hp;
        }
    }
    __syncthreads();

    float C[2][8][4];
#pragma unroll
    for (int mi = 0; mi < 2; ++mi)
#pragma unroll
        for (int nt = 0; nt < 8; ++nt)
#pragma unroll
            for (int e = 0; e < 4; ++e) C[mi][nt][e] = 0.f;

    mma_layer(C, smb, TB_NW0, 0, lane, wm, wn);
    __syncthreads();
    epi_relu(C, sm, nb0, lane, wm, wn);
    __syncthreads();
    mma_layer(C, smb, TB_NW1, 0, lane, wm, wn);
    __syncthreads();
    epi_relu(C, sm, nb1, lane, wm, wn);
    __syncthreads();
    mma_layer(C, smb, TB_NW2, 0, lane, wm, wn);

    float mu[2][2], rs[2][2];
    ln_stats(C, sm, nb2, t, lane, wm, wn, mu, rs);

    const int grp = lane >> 2, tig = lane & 3;
#pragma unroll
    for (int nt = 0; nt < 8; ++nt) {
        int col0 = wn * 64 + nt * 8 + tig * 2;
        float g0 = __ldg(ng + col0),     g1 = __ldg(ng + col0 + 1);
        float be0 = __ldg(nbeta + col0), be1 = __ldg(nbeta + col0 + 1);
#pragma unroll
        for (int mi = 0; mi < 2; ++mi) {
            int r1 = wm * 32 + mi * 16 + grp;
            if (r0 + r1 < natoms) {
                float2 o1 = {(C[mi][nt][0] - mu[mi][0]) * rs[mi][0] * g0 + be0,
                             (C[mi][nt][1] - mu[mi][0]) * rs[mi][0] * g1 + be1};
                *reinterpret_cast<float2*>(out + (r0 + r1) * 128 + col0) = o1;
            }
            if (r0 + r1 + 8 < natoms) {
                float2 o2 = {(C[mi][nt][2] - mu[mi][1]) * rs[mi][1] * g0 + be0,
                             (C[mi][nt][3] - mu[mi][1]) * rs[mi][1] * g1 + be1};
                *reinterpret_cast<float2*>(out + (r0 + r1 + 8) * 128 + col0) = o2;
            }
        }
    }
}

// ============================ launch ========================================
extern "C" void kernel_launch(void* const* d_in, const int* in_sizes, int n_in,
                              void* d_out, int out_size) {
    const float* x         = (const float*)d_in[0];
    const float* edge_attr = (const float*)d_in[1];
    const int*   receivers = (const int*)d_in[2];
    const int*   senders   = (const int*)d_in[3];

    int wi = 4;
    while (wi < n_in && in_sizes[wi] != 3 * 128 * 128) wi++;
    if (wi >= n_in) wi = (in_sizes[4] == 1) ? 5 : 4;

    const float* eW0   = (const float*)d_in[wi + 0];
    const float* eb0   = (const float*)d_in[wi + 1];
    const float* eW1   = (const float*)d_in[wi + 2];
    const float* eb1   = (const float*)d_in[wi + 3];
    const float* eW2   = (const float*)d_in[wi + 4];
    const float* eb2   = (const float*)d_in[wi + 5];
    const float* eg    = (const float*)d_in[wi + 6];
    const float* ebeta = (const float*)d_in[wi + 7];
    const float* nW0   = (const float*)d_in[wi + 8];
    const float* nb0   = (const float*)d_in[wi + 9];
    const float* nW1   = (const float*)d_in[wi + 10];
    const float* nb1   = (const float*)d_in[wi + 11];
    const float* nW2   = (const float*)d_in[wi + 12];
    const float* nb2   = (const float*)d_in[wi + 13];
    const float* ng    = (const float*)d_in[wi + 14];
    const float* nbeta = (const float*)d_in[wi + 15];

    int E      = in_sizes[2];
    int natoms = out_size / 128;
    int nblk   = (natoms + 63) / 64;

    prep_all<<<104, 256>>>(eW0, eW1, eW2, nW0, nW1, nW2);
    mpnn_pre<<<nblk, 128, SMEM_TOTAL>>>(x, natoms);
    mpnn_edge<<<E / 64, 128, SMEM_TOTAL>>>(edge_attr, receivers, senders,
                                           eb0, eb1, eb2, eg, ebeta);
    mpnn_node<<<nblk, 128, SMEM_TOTAL>>>(nb0, nb1, nb2, ng, nbeta,
                                         (float*)d_out, natoms);
}